// round 11
// baseline (speedup 1.0000x reference)
#include <cuda_runtime.h>
#include <math.h>
#include <stdint.h>

#define TT   2048
#define CC   512
#define HH   8
#define DHD  64
#define WINW 48
#define C3   1536
#define QB   32
#define BAND 128

// Scratch (device globals — no allocation allowed)
__device__ float g_qkv[TT * C3];
__device__ float g_y[TT * CC];
__device__ float g_x32[TT * CC];
__device__ float g_wqkv32[CC * C3];
__device__ float g_wout32[CC * CC];

// ---------------------------------------------------------------------------
__device__ __forceinline__ float to_tf32(float x) {
    float y;
    asm("cvt.rna.tf32.f32 %0, %1;" : "=f"(y) : "f"(x));
    return y;
}

__device__ __forceinline__ void mma_tf32(float& c0, float& c1, float& c2, float& c3,
                                         uint32_t a0, uint32_t a1, uint32_t a2, uint32_t a3,
                                         uint32_t b0, uint32_t b1) {
    asm volatile(
        "mma.sync.aligned.m16n8k8.row.col.f32.tf32.tf32.f32 "
        "{%0,%1,%2,%3}, {%4,%5,%6,%7}, {%8,%9}, {%0,%1,%2,%3};"
        : "+f"(c0), "+f"(c1), "+f"(c2), "+f"(c3)
        : "r"(a0), "r"(a1), "r"(a2), "r"(a3), "r"(b0), "r"(b1));
}

#define CP_ASYNC16(dst, src) \
    asm volatile("cp.async.cg.shared.global [%0], [%1], 16;\n" :: "r"(dst), "l"(src))
#define CP_COMMIT() asm volatile("cp.async.commit_group;\n" ::)
#define CP_WAIT2()  asm volatile("cp.async.wait_group 2;\n" ::)

// ---------------------------------------------------------------------------
// Prep: round x, W_qkv, W_out to tf32 (rna) into scratch copies.
// ---------------------------------------------------------------------------
#define XF4   (TT * CC / 4)
#define WQF4  (CC * C3 / 4)
#define WOF4  (CC * CC / 4)
#define PREPF4 (XF4 + WQF4 + WOF4)

__global__ void prep_tf32_kernel(const float4* __restrict__ x,
                                 const float4* __restrict__ wq,
                                 const float4* __restrict__ wo,
                                 float4* __restrict__ xo,
                                 float4* __restrict__ wqo,
                                 float4* __restrict__ woo) {
    int i = blockIdx.x * blockDim.x + threadIdx.x;
    if (i >= PREPF4) return;
    const float4* src;
    float4* dst;
    int j = i;
    if (j < XF4) { src = x; dst = xo; }
    else if (j < XF4 + WQF4) { j -= XF4; src = wq; dst = wqo; }
    else { j -= XF4 + WQF4; src = wo; dst = woo; }
    float4 v = src[j];
    v.x = to_tf32(v.x); v.y = to_tf32(v.y);
    v.z = to_tf32(v.z); v.w = to_tf32(v.w);
    dst[j] = v;
}

// Zero-fill for split-K atomic accumulation target.
__global__ void zero_kernel(float4* __restrict__ p, int n4) {
    int i = blockIdx.x * blockDim.x + threadIdx.x;
    if (i < n4) p[i] = make_float4(0.f, 0.f, 0.f, 0.f);
}

// ---------------------------------------------------------------------------
// TF32 GEMM (R9, proven): cp.async 4-stage, block 128x64, 8 warps,
// optional split-K with atomicAdd epilogue.
// ---------------------------------------------------------------------------
#define GBM 128
#define GBN 64
#define GBK 16
#define NSTAGE 4
#define A_ST (128 * 20)
#define B_ST (16 * 72)
#define GEMM_SMEM_BYTES ((NSTAGE * A_ST + NSTAGE * B_ST) * 4)

template<int M, int N, int K, int KSPLIT, bool ATOMIC>
__global__ void __launch_bounds__(256, 3) gemm_tf32_kernel(
    const float* __restrict__ A,
    const float* __restrict__ B,
    float* __restrict__ Cout)
{
    extern __shared__ float smemf[];
    float* As = smemf;
    float* Bs = smemf + NSTAGE * A_ST;

    const int t    = threadIdx.x;
    const int lane = t & 31;
    const int w    = t >> 5;
    const int wm   = (w >> 1) * 32;
    const int wn   = (w & 1) * 32;
    const int m0   = blockIdx.y * GBM;
    const int n0   = blockIdx.x * GBN;
    const int koff = blockIdx.z * (K / KSPLIT);
    const int lq   = lane >> 2;
    const int lr   = lane & 3;

    const int arow = t >> 1;
    const int ak8  = t & 1;
    const int brow = t >> 4;
    const int bcol = (t & 15) * 4;

    const float* Abase = A + (size_t)(m0 + arow) * K + koff + ak8 * 8;
    const float* Bbase = B + (size_t)(koff + brow) * N + n0 + bcol;

    uint32_t as_base = (uint32_t)__cvta_generic_to_shared(As) +
                       (arow * 20 + ak8 * 8) * 4;
    uint32_t bs_base = (uint32_t)__cvta_generic_to_shared(Bs) +
                       (brow * 72 + bcol) * 4;

    float c[2][4][4];
#pragma unroll
    for (int mt = 0; mt < 2; mt++)
#pragma unroll
        for (int nt = 0; nt < 4; nt++)
#pragma unroll
            for (int i = 0; i < 4; i++) c[mt][nt][i] = 0.f;

    const int NSTEP = (K / KSPLIT) / GBK;

#pragma unroll
    for (int p = 0; p < NSTAGE - 1; p++) {
        const float* asrc = Abase + p * GBK;
        uint32_t adst = as_base + p * A_ST * 4;
        CP_ASYNC16(adst, asrc);
        CP_ASYNC16(adst + 16, asrc + 4);
        const float* bsrc = Bbase + (size_t)p * GBK * N;
        CP_ASYNC16(bs_base + p * B_ST * 4, bsrc);
        CP_COMMIT();
    }

    for (int s = 0; s < NSTEP; s++) {
        CP_WAIT2();
        __syncthreads();

        if (s + NSTAGE - 1 < NSTEP) {
            const int stg = (s + NSTAGE - 1) & (NSTAGE - 1);
            const float* asrc = Abase + (s + NSTAGE - 1) * GBK;
            uint32_t adst = as_base + stg * A_ST * 4;
            CP_ASYNC16(adst, asrc);
            CP_ASYNC16(adst + 16, asrc + 4);
            const float* bsrc = Bbase + (size_t)(s + NSTAGE - 1) * GBK * N;
            CP_ASYNC16(bs_base + stg * B_ST * 4, bsrc);
        }
        CP_COMMIT();

        const float* AsS = As + (s & (NSTAGE - 1)) * A_ST;
        const float* BsS = Bs + (s & (NSTAGE - 1)) * B_ST;

#pragma unroll
        for (int kk8 = 0; kk8 < 2; kk8++) {
            const int kb = kk8 * 8;
            uint32_t af[2][4];
#pragma unroll
            for (int mt = 0; mt < 2; mt++) {
                const int r0 = (wm + mt * 16 + lq) * 20;
                af[mt][0] = __float_as_uint(AsS[r0 + kb + lr]);
                af[mt][1] = __float_as_uint(AsS[r0 + 160 + kb + lr]);
                af[mt][2] = __float_as_uint(AsS[r0 + kb + lr + 4]);
                af[mt][3] = __float_as_uint(AsS[r0 + 160 + kb + lr + 4]);
            }
            uint32_t bf[4][2];
#pragma unroll
            for (int nt = 0; nt < 4; nt++) {
                const int col = wn + nt * 8 + lq;
                bf[nt][0] = __float_as_uint(BsS[(kb + lr) * 72 + col]);
                bf[nt][1] = __float_as_uint(BsS[(kb + lr + 4) * 72 + col]);
            }
#pragma unroll
            for (int mt = 0; mt < 2; mt++)
#pragma unroll
                for (int nt = 0; nt < 4; nt++)
                    mma_tf32(c[mt][nt][0], c[mt][nt][1], c[mt][nt][2], c[mt][nt][3],
                             af[mt][0], af[mt][1], af[mt][2], af[mt][3],
                             bf[nt][0], bf[nt][1]);
        }
    }

#pragma unroll
    for (int mt = 0; mt < 2; mt++) {
#pragma unroll
        for (int nt = 0; nt < 4; nt++) {
            const int row0 = m0 + wm + mt * 16 + lq;
            const int col  = n0 + wn + nt * 8 + 2 * lr;
            if (ATOMIC) {
                atomicAdd(&Cout[(size_t)row0 * N + col],       c[mt][nt][0]);
                atomicAdd(&Cout[(size_t)row0 * N + col + 1],   c[mt][nt][1]);
                atomicAdd(&Cout[(size_t)(row0 + 8) * N + col],     c[mt][nt][2]);
                atomicAdd(&Cout[(size_t)(row0 + 8) * N + col + 1], c[mt][nt][3]);
            } else {
                *(float2*)&Cout[(size_t)row0 * N + col] =
                    make_float2(c[mt][nt][0], c[mt][nt][1]);
                *(float2*)&Cout[(size_t)(row0 + 8) * N + col] =
                    make_float2(c[mt][nt][2], c[mt][nt][3]);
            }
        }
    }
}

// ---------------------------------------------------------------------------
// Attention v6: chunked 3xTF32 tensor-core attention, 3 CTAs/SM.
// K band (and then V band) processed in two 64-row chunks through ONE shared
// 64x68 hi/lo buffer; Y accumulators persist in registers across V chunks.
//
// smem float layout (17440 floats = 69760 B):
//  [0,2176)       QH [32][68]        -> after Phase A: WH [32][132] (4224<=4352)
//  [2176,4352)    QL [32][68]
//  [4352,8704)    Kbuf-H [64][68]    -> VH chunk [64][68]
//  [8704,13056)   Kbuf-L [64][68]    -> VL chunk
//  [13056,17280)  S [32][132]        -> WL in place
//  [17280,17440)  nb[128], pts[32]
// ---------------------------------------------------------------------------
#define AST 68
#define BST 132
#define OFF_QH 0
#define OFF_QL 2176
#define OFF_KH 4352
#define OFF_KL 8704
#define OFF_S  13056
#define OFF_WH OFF_QH
#define OFF_WL OFF_S
#define OFF_VH OFF_KH
#define OFF_VL OFF_KL
#define OFF_IDX 17280
#define ATTN_SMEM_FLOATS (OFF_IDX + BAND + QB)
#define ATTN_SMEM_BYTES  (ATTN_SMEM_FLOATS * 4)

// stage one 64-row chunk (rows base..base+63 of nb) from qkv column block
// `src_off` into the hi/lo buffers at OFF_H/OFF_L, natural [r][AST] layout.
__device__ __forceinline__ void stage_chunk64(
    float* sm, const float* __restrict__ qkv, const int* nb,
    int base, int src_off, int off_h, int off_l, int t)
{
    const int r  = t & 63;
    const int d0 = (t >> 6) * 16;
    const float* src = qkv + (size_t)nb[base + r] * C3 + src_off + d0;
    float4 v0 = ((const float4*)src)[0];
    float4 v1 = ((const float4*)src)[1];
    float4 v2 = ((const float4*)src)[2];
    float4 v3 = ((const float4*)src)[3];
    float vv[16] = {v0.x, v0.y, v0.z, v0.w, v1.x, v1.y, v1.z, v1.w,
                    v2.x, v2.y, v2.z, v2.w, v3.x, v3.y, v3.z, v3.w};
    float hi[16], lo[16];
#pragma unroll
    for (int i = 0; i < 16; i++) {
        hi[i] = to_tf32(vv[i]);
        lo[i] = to_tf32(vv[i] - hi[i]);
    }
    const int o = r * AST + d0;
#pragma unroll
    for (int q = 0; q < 4; q++) {
        *(float4*)&sm[off_h + o + 4 * q] =
            make_float4(hi[4*q], hi[4*q+1], hi[4*q+2], hi[4*q+3]);
        *(float4*)&sm[off_l + o + 4 * q] =
            make_float4(lo[4*q], lo[4*q+1], lo[4*q+2], lo[4*q+3]);
    }
}

__global__ void __launch_bounds__(256, 3) attn6_kernel(
    const float* __restrict__ qkv,
    const int* __restrict__ perms,
    float* __restrict__ y)
{
    extern __shared__ float sm[];
    int* nb  = (int*)(sm + OFF_IDX);
    int* pts = nb + BAND;

    const int h    = blockIdx.y;
    const int t0   = blockIdx.x * QB;
    const int t    = threadIdx.x;
    const int lane = t & 31;
    const int w    = t >> 5;
    const int lq   = lane >> 2;
    const int lr   = lane & 3;

    const int* __restrict__ perm = perms + h * TT;

    // ---- index staging ----
    for (int i = t; i < BAND + QB; i += 256) {
        if (i < BAND) {
            int j  = t0 - WINW + i;
            int jc = min(max(j, 0), TT - 1);
            nb[i] = perm[jc];
        } else {
            pts[i - BAND] = perm[t0 + (i - BAND)];
        }
    }
    __syncthreads();

    // ---- stage Q (scaled) split hi/lo ----
    {
        const int row = t >> 3;
        const int d0  = (t & 7) * 8;
        const float* src = qkv + (size_t)pts[row] * C3 + h * DHD + d0;
        float4 v0 = *(const float4*)src;
        float4 v1 = *(const float4*)(src + 4);
        float vv[8] = {v0.x, v0.y, v0.z, v0.w, v1.x, v1.y, v1.z, v1.w};
        float hi[8], lo[8];
#pragma unroll
        for (int i = 0; i < 8; i++) {
            float s = vv[i] * 0.125f;
            hi[i] = to_tf32(s);
            lo[i] = to_tf32(s - hi[i]);
        }
        const int o = row * AST + d0;
        *(float4*)&sm[OFF_QH + o]     = make_float4(hi[0], hi[1], hi[2], hi[3]);
        *(float4*)&sm[OFF_QH + o + 4] = make_float4(hi[4], hi[5], hi[6], hi[7]);
        *(float4*)&sm[OFF_QL + o]     = make_float4(lo[0], lo[1], lo[2], lo[3]);
        *(float4*)&sm[OFF_QL + o + 4] = make_float4(lo[4], lo[5], lo[6], lo[7]);
    }

    // ---- Phase A: S = Q K^T in two 64-column chunks ----
    // warp layout: wmt = w&1 selects q-halves, wcol = (w>>1)*16 selects cols
    const int wmt  = w & 1;
    const int wcol = (w >> 1) * 16;

#pragma unroll
    for (int c = 0; c < 2; c++) {
        stage_chunk64(sm, qkv, nb, c * 64, CC + h * DHD, OFF_KH, OFF_KL, t);
        __syncthreads();

        float acc[2][4];
#pragma unroll
        for (int nt = 0; nt < 2; nt++)
#pragma unroll
            for (int i = 0; i < 4; i++) acc[nt][i] = 0.f;

#pragma unroll
        for (int kb = 0; kb < DHD; kb += 8) {
            uint32_t ah[4], al[4];
            const int r0 = (wmt * 16 + lq) * AST + kb;
            ah[0] = __float_as_uint(sm[OFF_QH + r0 + lr]);
            ah[1] = __float_as_uint(sm[OFF_QH + r0 + 8 * AST + lr]);
            ah[2] = __float_as_uint(sm[OFF_QH + r0 + lr + 4]);
            ah[3] = __float_as_uint(sm[OFF_QH + r0 + 8 * AST + lr + 4]);
            al[0] = __float_as_uint(sm[OFF_QL + r0 + lr]);
            al[1] = __float_as_uint(sm[OFF_QL + r0 + 8 * AST + lr]);
            al[2] = __float_as_uint(sm[OFF_QL + r0 + lr + 4]);
            al[3] = __float_as_uint(sm[OFF_QL + r0 + 8 * AST + lr + 4]);
            uint32_t bh[2][2], bl[2][2];
#pragma unroll
            for (int nt = 0; nt < 2; nt++) {
                const int co = (wcol + nt * 8 + lq) * AST + kb;
                bh[nt][0] = __float_as_uint(sm[OFF_KH + co + lr]);
                bh[nt][1] = __float_as_uint(sm[OFF_KH + co + lr + 4]);
                bl[nt][0] = __float_as_uint(sm[OFF_KL + co + lr]);
                bl[nt][1] = __float_as_uint(sm[OFF_KL + co + lr + 4]);
            }
#pragma unroll
            for (int nt = 0; nt < 2; nt++) {
                mma_tf32(acc[nt][0], acc[nt][1], acc[nt][2], acc[nt][3],
                         ah[0], ah[1], ah[2], ah[3], bh[nt][0], bh[nt][1]);
                mma_tf32(acc[nt][0], acc[nt][1], acc[nt][2], acc[nt][3],
                         ah[0], ah[1], ah[2], ah[3], bl[nt][0], bl[nt][1]);
                mma_tf32(acc[nt][0], acc[nt][1], acc[nt][2], acc[nt][3],
                         al[0], al[1], al[2], al[3], bh[nt][0], bh[nt][1]);
            }
        }
#pragma unroll
        for (int nt = 0; nt < 2; nt++) {
            const int q0  = wmt * 16 + lq;
            const int col = c * 64 + wcol + nt * 8 + 2 * lr;
            *(float2*)&sm[OFF_S + q0 * BST + col] = make_float2(acc[nt][0], acc[nt][1]);
            *(float2*)&sm[OFF_S + (q0 + 8) * BST + col] = make_float2(acc[nt][2], acc[nt][3]);
        }
        __syncthreads();
    }

    // ---- softmax (writes WH over Q region, WL in-place over S)
    //      + stage V chunk 0 into the freed K buffer (independent work) ----
    stage_chunk64(sm, qkv, nb, 0, 2 * CC + h * DHD, OFF_VH, OFF_VL, t);

    for (int qq = w; qq < QB; qq += 8) {
        const int pt = pts[qq];
        float v[4];
#pragma unroll
        for (int cc = 0; cc < 4; cc++) {
            const int r = lane + 32 * cc;
            const bool m = (r >= qq) && (r <= qq + 96) &&
                           ((unsigned)(t0 - WINW + r) < (unsigned)TT) &&
                           (nb[r] <= pt);
            v[cc] = m ? sm[OFF_S + qq * BST + r] : -INFINITY;
        }
        float mx = fmaxf(fmaxf(v[0], v[1]), fmaxf(v[2], v[3]));
#pragma unroll
        for (int off = 16; off; off >>= 1)
            mx = fmaxf(mx, __shfl_xor_sync(0xffffffffu, mx, off));
        float e[4], s = 0.f;
#pragma unroll
        for (int cc = 0; cc < 4; cc++) { e[cc] = __expf(v[cc] - mx); s += e[cc]; }
#pragma unroll
        for (int off = 16; off; off >>= 1)
            s += __shfl_xor_sync(0xffffffffu, s, off);
        const float inv = 1.f / s;
#pragma unroll
        for (int cc = 0; cc < 4; cc++) {
            const int r = lane + 32 * cc;
            const float wv = e[cc] * inv;
            const float hi = to_tf32(wv);
            sm[OFF_WH + qq * BST + r] = hi;
            sm[OFF_WL + qq * BST + r] = to_tf32(wv - hi);
        }
    }
    __syncthreads();

    // ---- Phase B: Y = W V in two 64-k chunks, accumulators persist ----
    const int wm = (w & 1) * 16;
    const int ng = (w >> 1) * 16;
    float cB[2][4];
#pragma unroll
    for (int nt = 0; nt < 2; nt++)
#pragma unroll
        for (int i = 0; i < 4; i++) cB[nt][i] = 0.f;

#pragma unroll
    for (int c = 0; c < 2; c++) {
        if (c == 1) {
            __syncthreads();   // PV0 done reading Vbuf
            stage_chunk64(sm, qkv, nb, 64, 2 * CC + h * DHD, OFF_VH, OFF_VL, t);
            __syncthreads();
        }
#pragma unroll
        for (int kbl = 0; kbl < 64; kbl += 8) {
            const int kb = c * 64 + kbl;
            uint32_t ah[4], al[4];
            const int r0 = (wm + lq) * BST + kb;
            ah[0] = __float_as_uint(sm[OFF_WH + r0 + lr]);
            ah[1] = __float_as_uint(sm[OFF_WH + r0 + 8 * BST + lr]);
            ah[2] = __float_as_uint(sm[OFF_WH + r0 + lr + 4]);
            ah[3] = __float_as_uint(sm[OFF_WH + r0 + 8 * BST + lr + 4]);
            al[0] = __float_as_uint(sm[OFF_WL + r0 + lr]);
            al[1] = __float_as_uint(sm[OFF_WL + r0 + 8 * BST + lr]);
            al[2] = __float_as_uint(sm[OFF_WL + r0 + lr + 4]);
            al[3] = __float_as_uint(sm[OFF_WL + r0 + 8 * BST + lr + 4]);
            uint32_t bh[2][2], bl[2][2];
#pragma unroll
            for (int nt = 0; nt < 2; nt++) {
                const int col = ng + nt * 8 + lq;
                bh[nt][0] = __float_as_uint(sm[OFF_VH + (kbl + lr) * AST + col]);
                bh[nt][1] = __float_as_uint(sm[OFF_VH + (kbl + lr + 4) * AST + col]);
                bl[nt][0] = __float_as_uint(sm[OFF_VL + (kbl + lr) * AST + col]);
                bl[nt][1] = __float_as_uint(sm[OFF_VL + (kbl + lr + 4) * AST + col]);
            }
#pragma unroll
            for (int nt = 0; nt < 2; nt++) {
                mma_tf32(cB[nt][0], cB[nt][1], cB[nt][2], cB[nt][3],
                         ah[0], ah[1], ah[2], ah[3], bh[nt][0], bh[nt][1]);
                mma_tf32(cB[nt][0], cB[nt][1], cB[nt][2], cB[nt][3],
                         ah[0], ah[1], ah[2], ah[3], bl[nt][0], bl[nt][1]);
                mma_tf32(cB[nt][0], cB[nt][1], cB[nt][2], cB[nt][3],
                         al[0], al[1], al[2], al[3], bh[nt][0], bh[nt][1]);
            }
        }
    }

    // ---- epilogue: scatter y (tf32-rounded for gemm2) ----
#pragma unroll
    for (int nt = 0; nt < 2; nt++) {
        const int d  = ng + nt * 8 + 2 * lr;
        const int q0 = wm + lq;
        *(float2*)&y[(size_t)pts[q0] * CC + h * DHD + d] =
            make_float2(to_tf32(cB[nt][0]), to_tf32(cB[nt][1]));
        *(float2*)&y[(size_t)pts[q0 + 8] * CC + h * DHD + d] =
            make_float2(to_tf32(cB[nt][2]), to_tf32(cB[nt][3]));
    }
}

// ---------------------------------------------------------------------------
extern "C" void kernel_launch(void* const* d_in, const int* in_sizes, int n_in,
                              void* d_out, int out_size) {
    (void)in_sizes; (void)n_in; (void)out_size;
    const float* x     = (const float*)d_in[0];
    const float* Wqkv  = (const float*)d_in[1];
    const float* Wout  = (const float*)d_in[2];
    const int*   perms = (const int*)d_in[3];
    float*       out   = (float*)d_out;

    float *qkv, *y, *x32, *wq32, *wo32;
    cudaGetSymbolAddress((void**)&qkv,  g_qkv);
    cudaGetSymbolAddress((void**)&y,    g_y);
    cudaGetSymbolAddress((void**)&x32,  g_x32);
    cudaGetSymbolAddress((void**)&wq32, g_wqkv32);
    cudaGetSymbolAddress((void**)&wo32, g_wout32);

    cudaFuncSetAttribute((const void*)gemm_tf32_kernel<TT, C3, CC, 1, false>,
                         cudaFuncAttributeMaxDynamicSharedMemorySize, GEMM_SMEM_BYTES);
    cudaFuncSetAttribute((const void*)gemm_tf32_kernel<TT, CC, CC, 2, true>,
                         cudaFuncAttributeMaxDynamicSharedMemorySize, GEMM_SMEM_BYTES);
    cudaFuncSetAttribute(attn6_kernel,
                         cudaFuncAttributeMaxDynamicSharedMemorySize, ATTN_SMEM_BYTES);

    // 0) round inputs to tf32; zero-fill split-K target
    prep_tf32_kernel<<<PREPF4 / 256, 256>>>(
        (const float4*)x, (const float4*)Wqkv, (const float4*)Wout,
        (float4*)x32, (float4*)wq32, (float4*)wo32);
    zero_kernel<<<(TT * CC / 4 + 255) / 256, 256>>>((float4*)out, TT * CC / 4);
    // 1) qkv = x @ W_qkv
    gemm_tf32_kernel<TT, C3, CC, 1, false>
        <<<dim3(C3 / GBN, TT / GBM, 1), 256, GEMM_SMEM_BYTES>>>(x32, wq32, qkv);
    // 2) attention (3 CTAs/SM, chunked staging)
    attn6_kernel<<<dim3(TT / QB, HH), 256, ATTN_SMEM_BYTES>>>(qkv, perms, y);
    // 3) out += y @ W_out (split-K=2, atomic accumulate)
    gemm_tf32_kernel<TT, CC, CC, 2, true>
        <<<dim3(CC / GBN, TT / GBM, 2), 256, GEMM_SMEM_BYTES>>>(y, wo32, out);
}

// round 12
// speedup vs baseline: 1.1046x; 1.1046x over previous
#include <cuda_runtime.h>
#include <math.h>
#include <stdint.h>

#define TT   2048
#define CC   512
#define HH   8
#define DHD  64
#define WINW 48
#define C3   1536
#define QB   32
#define BAND 128

// Scratch (device globals — no allocation allowed)
__device__ float g_qkv[TT * C3];
__device__ float g_y[TT * CC];
__device__ float g_x32[TT * CC];      // tf32-rounded x, 8-chunk pair-interleaved
__device__ float g_wqkv32[CC * C3];   // tf32-rounded W_qkv (plain)
__device__ float g_wout32[CC * CC];   // tf32-rounded W_out (plain)

// ---------------------------------------------------------------------------
__device__ __forceinline__ float to_tf32(float x) {
    float y;
    asm("cvt.rna.tf32.f32 %0, %1;" : "=f"(y) : "f"(x));
    return y;
}

__device__ __forceinline__ void mma_tf32(float& c0, float& c1, float& c2, float& c3,
                                         uint32_t a0, uint32_t a1, uint32_t a2, uint32_t a3,
                                         uint32_t b0, uint32_t b1) {
    asm volatile(
        "mma.sync.aligned.m16n8k8.row.col.f32.tf32.tf32.f32 "
        "{%0,%1,%2,%3}, {%4,%5,%6,%7}, {%8,%9}, {%0,%1,%2,%3};"
        : "+f"(c0), "+f"(c1), "+f"(c2), "+f"(c3)
        : "r"(a0), "r"(a1), "r"(a2), "r"(a3), "r"(b0), "r"(b1));
}

#define CP_ASYNC16(dst, src) \
    asm volatile("cp.async.cg.shared.global [%0], [%1], 16;\n" :: "r"(dst), "l"(src))
#define CP_COMMIT() asm volatile("cp.async.commit_group;\n" ::)
#define CP_WAIT2()  asm volatile("cp.async.wait_group 2;\n" ::)

// ---------------------------------------------------------------------------
// Prep: round to tf32 (rna). x additionally pair-interleaved per 8-chunk:
// out chunk order = (k0,k4),(k1,k5),(k2,k6),(k3,k7). Also zeros `out` for
// the split-K atomic GEMM. One flat grid over 4 tasks.
// ---------------------------------------------------------------------------
#define XCH   (TT * CC / 8)          // 131072  (8 floats per thread)
#define WQF4  (CC * C3 / 4)          // 196608
#define WOF4  (CC * CC / 4)          // 65536
#define OUTF4 (TT * CC / 4)          // 262144
#define PREPTH (XCH + WQF4 + WOF4 + OUTF4)   // 655360

__global__ void prep_tf32_kernel(const float4* __restrict__ x,
                                 const float4* __restrict__ wq,
                                 const float4* __restrict__ wo,
                                 float4* __restrict__ xo,
                                 float4* __restrict__ wqo,
                                 float4* __restrict__ woo,
                                 float4* __restrict__ outz) {
    int i = blockIdx.x * blockDim.x + threadIdx.x;
    if (i >= PREPTH) return;
    if (i < XCH) {
        // interleave one 8-float chunk of x
        const float4 a = x[2 * i];
        const float4 b = x[2 * i + 1];
        float4 o0, o1;
        o0.x = to_tf32(a.x); o0.y = to_tf32(b.x);   // (k0, k4)
        o0.z = to_tf32(a.y); o0.w = to_tf32(b.y);   // (k1, k5)
        o1.x = to_tf32(a.z); o1.y = to_tf32(b.z);   // (k2, k6)
        o1.z = to_tf32(a.w); o1.w = to_tf32(b.w);   // (k3, k7)
        xo[2 * i]     = o0;
        xo[2 * i + 1] = o1;
        return;
    }
    i -= XCH;
    if (i < WQF4) {
        float4 v = wq[i];
        v.x = to_tf32(v.x); v.y = to_tf32(v.y);
        v.z = to_tf32(v.z); v.w = to_tf32(v.w);
        wqo[i] = v;
        return;
    }
    i -= WQF4;
    if (i < WOF4) {
        float4 v = wo[i];
        v.x = to_tf32(v.x); v.y = to_tf32(v.y);
        v.z = to_tf32(v.z); v.w = to_tf32(v.w);
        woo[i] = v;
        return;
    }
    i -= WOF4;
    outz[i] = make_float4(0.f, 0.f, 0.f, 0.f);
}

// ---------------------------------------------------------------------------
// TF32 GEMM: cp.async 4-stage, block 128x64, 8 warps. Split-K (atomicAdd)
// optional. AINTER: A gmem layout is 8-chunk pair-interleaved -> A fragment
// loads are LDS.64 (pitch 24 floats, conflict-free).
// ---------------------------------------------------------------------------
#define GBM 128
#define GBN 64
#define GBK 16
#define NSTAGE 4
#define B_ST (16 * 72)

template<int M, int N, int K, int KSPLIT, bool ATOMIC, bool AINTER>
__global__ void __launch_bounds__(256, 3) gemm_tf32_kernel(
    const float* __restrict__ A,
    const float* __restrict__ B,
    float* __restrict__ Cout)
{
    constexpr int APITCH = AINTER ? 24 : 20;
    constexpr int A_STG  = 128 * APITCH;

    extern __shared__ float smemf[];
    float* As = smemf;
    float* Bs = smemf + NSTAGE * A_STG;

    const int t    = threadIdx.x;
    const int lane = t & 31;
    const int w    = t >> 5;
    const int wm   = (w >> 1) * 32;
    const int wn   = (w & 1) * 32;
    const int m0   = blockIdx.y * GBM;
    const int n0   = blockIdx.x * GBN;
    const int koff = blockIdx.z * (K / KSPLIT);
    const int lq   = lane >> 2;
    const int lr   = lane & 3;

    const int arow = t >> 1;
    const int ak8  = t & 1;
    const int brow = t >> 4;
    const int bcol = (t & 15) * 4;

    const float* Abase = A + (size_t)(m0 + arow) * K + koff + ak8 * 8;
    const float* Bbase = B + (size_t)(koff + brow) * N + n0 + bcol;

    uint32_t as_base = (uint32_t)__cvta_generic_to_shared(As) +
                       (arow * APITCH + ak8 * 8) * 4;
    uint32_t bs_base = (uint32_t)__cvta_generic_to_shared(Bs) +
                       (brow * 72 + bcol) * 4;

    float c[2][4][4];
#pragma unroll
    for (int mt = 0; mt < 2; mt++)
#pragma unroll
        for (int nt = 0; nt < 4; nt++)
#pragma unroll
            for (int i = 0; i < 4; i++) c[mt][nt][i] = 0.f;

    const int NSTEP = (K / KSPLIT) / GBK;

#pragma unroll
    for (int p = 0; p < NSTAGE - 1; p++) {
        const float* asrc = Abase + p * GBK;
        uint32_t adst = as_base + p * A_STG * 4;
        CP_ASYNC16(adst, asrc);
        CP_ASYNC16(adst + 16, asrc + 4);
        const float* bsrc = Bbase + (size_t)p * GBK * N;
        CP_ASYNC16(bs_base + p * B_ST * 4, bsrc);
        CP_COMMIT();
    }

    for (int s = 0; s < NSTEP; s++) {
        CP_WAIT2();
        __syncthreads();

        if (s + NSTAGE - 1 < NSTEP) {
            const int stg = (s + NSTAGE - 1) & (NSTAGE - 1);
            const float* asrc = Abase + (s + NSTAGE - 1) * GBK;
            uint32_t adst = as_base + stg * A_STG * 4;
            CP_ASYNC16(adst, asrc);
            CP_ASYNC16(adst + 16, asrc + 4);
            const float* bsrc = Bbase + (size_t)(s + NSTAGE - 1) * GBK * N;
            CP_ASYNC16(bs_base + stg * B_ST * 4, bsrc);
        }
        CP_COMMIT();

        const float* AsS = As + (s & (NSTAGE - 1)) * A_STG;
        const float* BsS = Bs + (s & (NSTAGE - 1)) * B_ST;

#pragma unroll
        for (int kk8 = 0; kk8 < 2; kk8++) {
            const int kb = kk8 * 8;
            uint32_t af[2][4];
#pragma unroll
            for (int mt = 0; mt < 2; mt++) {
                if (AINTER) {
                    const float2* AsS2 = (const float2*)AsS;
                    const int r0 = (wm + mt * 16 + lq) * (APITCH / 2) + kk8 * 4 + lr;
                    const float2 p0 = AsS2[r0];
                    const float2 p1 = AsS2[r0 + 8 * (APITCH / 2)];
                    af[mt][0] = __float_as_uint(p0.x);
                    af[mt][1] = __float_as_uint(p1.x);
                    af[mt][2] = __float_as_uint(p0.y);
                    af[mt][3] = __float_as_uint(p1.y);
                } else {
                    const int r0 = (wm + mt * 16 + lq) * APITCH;
                    af[mt][0] = __float_as_uint(AsS[r0 + kb + lr]);
                    af[mt][1] = __float_as_uint(AsS[r0 + 8 * APITCH + kb + lr]);
                    af[mt][2] = __float_as_uint(AsS[r0 + kb + lr + 4]);
                    af[mt][3] = __float_as_uint(AsS[r0 + 8 * APITCH + kb + lr + 4]);
                }
            }
            uint32_t bf[4][2];
#pragma unroll
            for (int nt = 0; nt < 4; nt++) {
                const int col = wn + nt * 8 + lq;
                bf[nt][0] = __float_as_uint(BsS[(kb + lr) * 72 + col]);
                bf[nt][1] = __float_as_uint(BsS[(kb + lr + 4) * 72 + col]);
            }
#pragma unroll
            for (int mt = 0; mt < 2; mt++)
#pragma unroll
                for (int nt = 0; nt < 4; nt++)
                    mma_tf32(c[mt][nt][0], c[mt][nt][1], c[mt][nt][2], c[mt][nt][3],
                             af[mt][0], af[mt][1], af[mt][2], af[mt][3],
                             bf[nt][0], bf[nt][1]);
        }
    }

#pragma unroll
    for (int mt = 0; mt < 2; mt++) {
#pragma unroll
        for (int nt = 0; nt < 4; nt++) {
            const int row0 = m0 + wm + mt * 16 + lq;
            const int col  = n0 + wn + nt * 8 + 2 * lr;
            if (ATOMIC) {
                atomicAdd(&Cout[(size_t)row0 * N + col],       c[mt][nt][0]);
                atomicAdd(&Cout[(size_t)row0 * N + col + 1],   c[mt][nt][1]);
                atomicAdd(&Cout[(size_t)(row0 + 8) * N + col],     c[mt][nt][2]);
                atomicAdd(&Cout[(size_t)(row0 + 8) * N + col + 1], c[mt][nt][3]);
            } else {
                *(float2*)&Cout[(size_t)row0 * N + col] =
                    make_float2(c[mt][nt][0], c[mt][nt][1]);
                *(float2*)&Cout[(size_t)(row0 + 8) * N + col] =
                    make_float2(c[mt][nt][2], c[mt][nt][3]);
            }
        }
    }
}

#define G1_SMEM_BYTES ((NSTAGE * (128 * 24) + NSTAGE * B_ST) * 4)   // 67584
#define G2_SMEM_BYTES ((NSTAGE * (128 * 20) + NSTAGE * B_ST) * 4)   // 59392

// ---------------------------------------------------------------------------
// Attention v5 (R9, best known = 28.4us): pre-split 3xTF32 tensor-core,
// V register-prefetch overlapping Phase A, natural V layout.
// ---------------------------------------------------------------------------
#define AST 68
#define BST 132
#define OFF_QH 0
#define OFF_QL 2176
#define OFF_KH 4352
#define OFF_KL 13056
#define OFF_S  21760
#define OFF_WH OFF_QH
#define OFF_WL OFF_S
#define OFF_VH OFF_KH
#define OFF_VL OFF_KL
#define OFF_IDX 25984
#define ATTN_SMEM_FLOATS (OFF_IDX + BAND + QB)
#define ATTN_SMEM_BYTES  (ATTN_SMEM_FLOATS * 4)

__global__ void __launch_bounds__(256, 2) attn5_kernel(
    const float* __restrict__ qkv,
    const int* __restrict__ perms,
    float* __restrict__ y)
{
    extern __shared__ float sm[];
    int* nb  = (int*)(sm + OFF_IDX);
    int* pts = nb + BAND;

    const int h    = blockIdx.y;
    const int t0   = blockIdx.x * QB;
    const int t    = threadIdx.x;
    const int lane = t & 31;
    const int w    = t >> 5;
    const int lq   = lane >> 2;
    const int lr   = lane & 3;

    const int* __restrict__ perm = perms + h * TT;

    // ---- index staging ----
    for (int i = t; i < BAND + QB; i += 256) {
        if (i < BAND) {
            int j  = t0 - WINW + i;
            int jc = min(max(j, 0), TT - 1);
            nb[i] = perm[jc];
        } else {
            pts[i - BAND] = perm[t0 + (i - BAND)];
        }
    }
    __syncthreads();

    // ---- stage Q (scaled) split hi/lo ----
    {
        const int row = t >> 3;
        const int d0  = (t & 7) * 8;
        const float* src = qkv + (size_t)pts[row] * C3 + h * DHD + d0;
        float4 v0 = *(const float4*)src;
        float4 v1 = *(const float4*)(src + 4);
        float vv[8] = {v0.x, v0.y, v0.z, v0.w, v1.x, v1.y, v1.z, v1.w};
        float hi[8], lo[8];
#pragma unroll
        for (int i = 0; i < 8; i++) {
            float s = vv[i] * 0.125f;
            hi[i] = to_tf32(s);
            lo[i] = to_tf32(s - hi[i]);
        }
        const int o = row * AST + d0;
        *(float4*)&sm[OFF_QH + o]     = make_float4(hi[0], hi[1], hi[2], hi[3]);
        *(float4*)&sm[OFF_QH + o + 4] = make_float4(hi[4], hi[5], hi[6], hi[7]);
        *(float4*)&sm[OFF_QL + o]     = make_float4(lo[0], lo[1], lo[2], lo[3]);
        *(float4*)&sm[OFF_QL + o + 4] = make_float4(lo[4], lo[5], lo[6], lo[7]);
    }
    // ---- stage K split hi/lo ----
#pragma unroll
    for (int it = 0; it < 4; it++) {
        const int r  = it * 32 + (t >> 3);
        const int d0 = (t & 7) * 8;
        const float* src = qkv + (size_t)nb[r] * C3 + CC + h * DHD + d0;
        float4 v0 = *(const float4*)src;
        float4 v1 = *(const float4*)(src + 4);
        float vv[8] = {v0.x, v0.y, v0.z, v0.w, v1.x, v1.y, v1.z, v1.w};
        float hi[8], lo[8];
#pragma unroll
        for (int i = 0; i < 8; i++) {
            hi[i] = to_tf32(vv[i]);
            lo[i] = to_tf32(vv[i] - hi[i]);
        }
        const int o = r * AST + d0;
        *(float4*)&sm[OFF_KH + o]     = make_float4(hi[0], hi[1], hi[2], hi[3]);
        *(float4*)&sm[OFF_KH + o + 4] = make_float4(hi[4], hi[5], hi[6], hi[7]);
        *(float4*)&sm[OFF_KL + o]     = make_float4(lo[0], lo[1], lo[2], lo[3]);
        *(float4*)&sm[OFF_KL + o + 4] = make_float4(lo[4], lo[5], lo[6], lo[7]);
    }

    // ---- prefetch V into registers (LDGs overlap Phase A) ----
    float2 vr[16];
#pragma unroll
    for (int it = 0; it < 16; it++) {
        const int r = it * 8 + w;
        vr[it] = *(const float2*)&qkv[(size_t)nb[r] * C3 + 2 * CC + h * DHD + 2 * lane];
    }
    __syncthreads();

    // ---- Phase A: S = Q K^T, 3xTF32 ----
    {
        float c[2][2][4];
#pragma unroll
        for (int mt = 0; mt < 2; mt++)
#pragma unroll
            for (int nt = 0; nt < 2; nt++)
#pragma unroll
                for (int i = 0; i < 4; i++) c[mt][nt][i] = 0.f;

#pragma unroll
        for (int kb = 0; kb < DHD; kb += 8) {
            uint32_t ah[2][4], al[2][4];
#pragma unroll
            for (int mt = 0; mt < 2; mt++) {
                const int r0 = (mt * 16 + lq) * AST + kb;
                ah[mt][0] = __float_as_uint(sm[OFF_QH + r0 + lr]);
                ah[mt][1] = __float_as_uint(sm[OFF_QH + r0 + 8 * AST + lr]);
                ah[mt][2] = __float_as_uint(sm[OFF_QH + r0 + lr + 4]);
                ah[mt][3] = __float_as_uint(sm[OFF_QH + r0 + 8 * AST + lr + 4]);
                al[mt][0] = __float_as_uint(sm[OFF_QL + r0 + lr]);
                al[mt][1] = __float_as_uint(sm[OFF_QL + r0 + 8 * AST + lr]);
                al[mt][2] = __float_as_uint(sm[OFF_QL + r0 + lr + 4]);
                al[mt][3] = __float_as_uint(sm[OFF_QL + r0 + 8 * AST + lr + 4]);
            }
            uint32_t bh[2][2], bl[2][2];
#pragma unroll
            for (int nt = 0; nt < 2; nt++) {
                const int co = (w * 16 + nt * 8 + lq) * AST + kb;
                bh[nt][0] = __float_as_uint(sm[OFF_KH + co + lr]);
                bh[nt][1] = __float_as_uint(sm[OFF_KH + co + lr + 4]);
                bl[nt][0] = __float_as_uint(sm[OFF_KL + co + lr]);
                bl[nt][1] = __float_as_uint(sm[OFF_KL + co + lr + 4]);
            }
#pragma unroll
            for (int mt = 0; mt < 2; mt++)
#pragma unroll
                for (int nt = 0; nt < 2; nt++) {
                    mma_tf32(c[mt][nt][0], c[mt][nt][1], c[mt][nt][2], c[mt][nt][3],
                             ah[mt][0], ah[mt][1], ah[mt][2], ah[mt][3],
                             bh[nt][0], bh[nt][1]);
                    mma_tf32(c[mt][nt][0], c[mt][nt][1], c[mt][nt][2], c[mt][nt][3],
                             ah[mt][0], ah[mt][1], ah[mt][2], ah[mt][3],
                             bl[nt][0], bl[nt][1]);
                    mma_tf32(c[mt][nt][0], c[mt][nt][1], c[mt][nt][2], c[mt][nt][3],
                             al[mt][0], al[mt][1], al[mt][2], al[mt][3],
                             bh[nt][0], bh[nt][1]);
                }
        }
#pragma unroll
        for (int mt = 0; mt < 2; mt++)
#pragma unroll
            for (int nt = 0; nt < 2; nt++) {
                const int q0  = mt * 16 + lq;
                const int col = w * 16 + nt * 8 + 2 * lr;
                *(float2*)&sm[OFF_S + q0 * BST + col] =
                    make_float2(c[mt][nt][0], c[mt][nt][1]);
                *(float2*)&sm[OFF_S + (q0 + 8) * BST + col] =
                    make_float2(c[mt][nt][2], c[mt][nt][3]);
            }
    }
    __syncthreads();

    // ---- store V from registers, split hi/lo, natural [r][68] layout ----
#pragma unroll
    for (int it = 0; it < 16; it++) {
        const int r = it * 8 + w;
        const float2 vv = vr[it];
        float hx = to_tf32(vv.x), lx = to_tf32(vv.x - hx);
        float hy = to_tf32(vv.y), ly = to_tf32(vv.y - hy);
        *(float2*)&sm[OFF_VH + r * AST + 2 * lane] = make_float2(hx, hy);
        *(float2*)&sm[OFF_VL + r * AST + 2 * lane] = make_float2(lx, ly);
    }

    // ---- masked softmax; W split (WH over Q region, WL in-place over S) ----
    for (int qq = w; qq < QB; qq += 8) {
        const int pt = pts[qq];
        float v[4];
#pragma unroll
        for (int cc = 0; cc < 4; cc++) {
            const int r = lane + 32 * cc;
            const bool m = (r >= qq) && (r <= qq + 96) &&
                           ((unsigned)(t0 - WINW + r) < (unsigned)TT) &&
                           (nb[r] <= pt);
            v[cc] = m ? sm[OFF_S + qq * BST + r] : -INFINITY;
        }
        float mx = fmaxf(fmaxf(v[0], v[1]), fmaxf(v[2], v[3]));
#pragma unroll
        for (int off = 16; off; off >>= 1)
            mx = fmaxf(mx, __shfl_xor_sync(0xffffffffu, mx, off));
        float e[4], s = 0.f;
#pragma unroll
        for (int cc = 0; cc < 4; cc++) { e[cc] = __expf(v[cc] - mx); s += e[cc]; }
#pragma unroll
        for (int off = 16; off; off >>= 1)
            s += __shfl_xor_sync(0xffffffffu, s, off);
        const float inv = 1.f / s;
#pragma unroll
        for (int cc = 0; cc < 4; cc++) {
            const int r = lane + 32 * cc;
            const float wv = e[cc] * inv;
            const float hi = to_tf32(wv);
            sm[OFF_WH + qq * BST + r] = hi;
            sm[OFF_WL + qq * BST + r] = to_tf32(wv - hi);
        }
    }
    __syncthreads();

    // ---- Phase B: Y = W V, 3xTF32 (V natural [k=r][n=d]) ----
    {
        const int wm = (w & 1) * 16;
        const int ng = (w >> 1) * 16;
        float c[2][4];
#pragma unroll
        for (int nt = 0; nt < 2; nt++)
#pragma unroll
            for (int i = 0; i < 4; i++) c[nt][i] = 0.f;

#pragma unroll
        for (int kb = 0; kb < BAND; kb += 8) {
            uint32_t ah[4], al[4];
            const int r0 = (wm + lq) * BST + kb;
            ah[0] = __float_as_uint(sm[OFF_WH + r0 + lr]);
            ah[1] = __float_as_uint(sm[OFF_WH + r0 + 8 * BST + lr]);
            ah[2] = __float_as_uint(sm[OFF_WH + r0 + lr + 4]);
            ah[3] = __float_as_uint(sm[OFF_WH + r0 + 8 * BST + lr + 4]);
            al[0] = __float_as_uint(sm[OFF_WL + r0 + lr]);
            al[1] = __float_as_uint(sm[OFF_WL + r0 + 8 * BST + lr]);
            al[2] = __float_as_uint(sm[OFF_WL + r0 + lr + 4]);
            al[3] = __float_as_uint(sm[OFF_WL + r0 + 8 * BST + lr + 4]);
            uint32_t bh[2][2], bl[2][2];
#pragma unroll
            for (int nt = 0; nt < 2; nt++) {
                const int col = ng + nt * 8 + lq;
                bh[nt][0] = __float_as_uint(sm[OFF_VH + (kb + lr) * AST + col]);
                bh[nt][1] = __float_as_uint(sm[OFF_VH + (kb + lr + 4) * AST + col]);
                bl[nt][0] = __float_as_uint(sm[OFF_VL + (kb + lr) * AST + col]);
                bl[nt][1] = __float_as_uint(sm[OFF_VL + (kb + lr + 4) * AST + col]);
            }
#pragma unroll
            for (int nt = 0; nt < 2; nt++) {
                mma_tf32(c[nt][0], c[nt][1], c[nt][2], c[nt][3],
                         ah[0], ah[1], ah[2], ah[3], bh[nt][0], bh[nt][1]);
                mma_tf32(c[nt][0], c[nt][1], c[nt][2], c[nt][3],
                         ah[0], ah[1], ah[2], ah[3], bl[nt][0], bl[nt][1]);
                mma_tf32(c[nt][0], c[nt][1], c[nt][2], c[nt][3],
                         al[0], al[1], al[2], al[3], bh[nt][0], bh[nt][1]);
            }
        }

#pragma unroll
        for (int nt = 0; nt < 2; nt++) {
            const int d  = ng + nt * 8 + 2 * lr;
            const int q0 = wm + lq;
            *(float2*)&y[(size_t)pts[q0] * CC + h * DHD + d] =
                make_float2(to_tf32(c[nt][0]), to_tf32(c[nt][1]));
            *(float2*)&y[(size_t)pts[q0 + 8] * CC + h * DHD + d] =
                make_float2(to_tf32(c[nt][2]), to_tf32(c[nt][3]));
        }
    }
}

// ---------------------------------------------------------------------------
extern "C" void kernel_launch(void* const* d_in, const int* in_sizes, int n_in,
                              void* d_out, int out_size) {
    (void)in_sizes; (void)n_in; (void)out_size;
    const float* x     = (const float*)d_in[0];
    const float* Wqkv  = (const float*)d_in[1];
    const float* Wout  = (const float*)d_in[2];
    const int*   perms = (const int*)d_in[3];
    float*       out   = (float*)d_out;

    float *qkv, *y, *x32, *wq32, *wo32;
    cudaGetSymbolAddress((void**)&qkv,  g_qkv);
    cudaGetSymbolAddress((void**)&y,    g_y);
    cudaGetSymbolAddress((void**)&x32,  g_x32);
    cudaGetSymbolAddress((void**)&wq32, g_wqkv32);
    cudaGetSymbolAddress((void**)&wo32, g_wout32);

    cudaFuncSetAttribute((const void*)gemm_tf32_kernel<TT, C3, CC, 1, false, true>,
                         cudaFuncAttributeMaxDynamicSharedMemorySize, G1_SMEM_BYTES);
    cudaFuncSetAttribute((const void*)gemm_tf32_kernel<TT, CC, CC, 2, true, false>,
                         cudaFuncAttributeMaxDynamicSharedMemorySize, G2_SMEM_BYTES);
    cudaFuncSetAttribute(attn5_kernel,
                         cudaFuncAttributeMaxDynamicSharedMemorySize, ATTN_SMEM_BYTES);

    // 0) tf32-round + interleave x, round weights, zero split-K target
    prep_tf32_kernel<<<(PREPTH + 255) / 256, 256>>>(
        (const float4*)x, (const float4*)Wqkv, (const float4*)Wout,
        (float4*)x32, (float4*)wq32, (float4*)wo32, (float4*)out);
    // 1) qkv = x @ W_qkv  (interleaved-A fragment path)
    gemm_tf32_kernel<TT, C3, CC, 1, false, true>
        <<<dim3(C3 / GBN, TT / GBM, 1), 256, G1_SMEM_BYTES>>>(x32, wq32, qkv);
    // 2) attention (attn5, best known)
    attn5_kernel<<<dim3(TT / QB, HH), 256, ATTN_SMEM_BYTES>>>(qkv, perms, y);
    // 3) out += y @ W_out (split-K=2, atomic accumulate)
    gemm_tf32_kernel<TT, CC, CC, 2, true, false>
        <<<dim3(CC / GBN, TT / GBM, 2), 256, G2_SMEM_BYTES>>>(y, wo32, out);
}

// round 13
// speedup vs baseline: 1.1318x; 1.0246x over previous
#include <cuda_runtime.h>
#include <math.h>
#include <stdint.h>

#define TT   2048
#define CC   512
#define HH   8
#define DHD  64
#define WINW 48
#define C3   1536
#define QB   32
#define BAND 128

// Scratch (device globals — no allocation allowed)
__device__ float g_qkv[TT * C3];
__device__ float g_y[TT * CC];
__device__ float g_x32[TT * CC];      // tf32-rounded x, 8-chunk pair-interleaved
__device__ float g_wqkv32[CC * C3];   // tf32-rounded W_qkv (plain)
__device__ float g_wout32[CC * CC];   // tf32-rounded W_out (plain)

// ---------------------------------------------------------------------------
__device__ __forceinline__ float to_tf32(float x) {
    float y;
    asm("cvt.rna.tf32.f32 %0, %1;" : "=f"(y) : "f"(x));
    return y;
}

__device__ __forceinline__ void split_tf32(float v, uint32_t& hi, uint32_t& lo) {
    float h = to_tf32(v);
    float l = to_tf32(v - h);
    hi = __float_as_uint(h);
    lo = __float_as_uint(l);
}

__device__ __forceinline__ void mma_tf32(float& c0, float& c1, float& c2, float& c3,
                                         uint32_t a0, uint32_t a1, uint32_t a2, uint32_t a3,
                                         uint32_t b0, uint32_t b1) {
    asm volatile(
        "mma.sync.aligned.m16n8k8.row.col.f32.tf32.tf32.f32 "
        "{%0,%1,%2,%3}, {%4,%5,%6,%7}, {%8,%9}, {%0,%1,%2,%3};"
        : "+f"(c0), "+f"(c1), "+f"(c2), "+f"(c3)
        : "r"(a0), "r"(a1), "r"(a2), "r"(a3), "r"(b0), "r"(b1));
}

#define CP_ASYNC16(dst, src) \
    asm volatile("cp.async.cg.shared.global [%0], [%1], 16;\n" :: "r"(dst), "l"(src))
#define CP_COMMIT() asm volatile("cp.async.commit_group;\n" ::)
#define CP_WAIT2()  asm volatile("cp.async.wait_group 2;\n" ::)

// ---------------------------------------------------------------------------
// Prep: tf32-round x (pair-interleaved), W_qkv, W_out; zero `out`.
// ---------------------------------------------------------------------------
#define XCH   (TT * CC / 8)
#define WQF4  (CC * C3 / 4)
#define WOF4  (CC * CC / 4)
#define OUTF4 (TT * CC / 4)
#define PREPTH (XCH + WQF4 + WOF4 + OUTF4)

__global__ void prep_tf32_kernel(const float4* __restrict__ x,
                                 const float4* __restrict__ wq,
                                 const float4* __restrict__ wo,
                                 float4* __restrict__ xo,
                                 float4* __restrict__ wqo,
                                 float4* __restrict__ woo,
                                 float4* __restrict__ outz) {
    int i = blockIdx.x * blockDim.x + threadIdx.x;
    if (i >= PREPTH) return;
    if (i < XCH) {
        const float4 a = x[2 * i];
        const float4 b = x[2 * i + 1];
        float4 o0, o1;
        o0.x = to_tf32(a.x); o0.y = to_tf32(b.x);
        o0.z = to_tf32(a.y); o0.w = to_tf32(b.y);
        o1.x = to_tf32(a.z); o1.y = to_tf32(b.z);
        o1.z = to_tf32(a.w); o1.w = to_tf32(b.w);
        xo[2 * i]     = o0;
        xo[2 * i + 1] = o1;
        return;
    }
    i -= XCH;
    if (i < WQF4) {
        float4 v = wq[i];
        v.x = to_tf32(v.x); v.y = to_tf32(v.y);
        v.z = to_tf32(v.z); v.w = to_tf32(v.w);
        wqo[i] = v;
        return;
    }
    i -= WQF4;
    if (i < WOF4) {
        float4 v = wo[i];
        v.x = to_tf32(v.x); v.y = to_tf32(v.y);
        v.z = to_tf32(v.z); v.w = to_tf32(v.w);
        woo[i] = v;
        return;
    }
    i -= WOF4;
    outz[i] = make_float4(0.f, 0.f, 0.f, 0.f);
}

// ---------------------------------------------------------------------------
// TF32 GEMM (R12): cp.async 4-stage, block 128x64, 8 warps; split-K atomic
// option; AINTER = pair-interleaved A layout (LDS.64 fragments).
// ---------------------------------------------------------------------------
#define GBM 128
#define GBN 64
#define GBK 16
#define NSTAGE 4
#define B_ST (16 * 72)

template<int M, int N, int K, int KSPLIT, bool ATOMIC, bool AINTER>
__global__ void __launch_bounds__(256, 3) gemm_tf32_kernel(
    const float* __restrict__ A,
    const float* __restrict__ B,
    float* __restrict__ Cout)
{
    constexpr int APITCH = AINTER ? 24 : 20;
    constexpr int A_STG  = 128 * APITCH;

    extern __shared__ float smemf[];
    float* As = smemf;
    float* Bs = smemf + NSTAGE * A_STG;

    const int t    = threadIdx.x;
    const int lane = t & 31;
    const int w    = t >> 5;
    const int wm   = (w >> 1) * 32;
    const int wn   = (w & 1) * 32;
    const int m0   = blockIdx.y * GBM;
    const int n0   = blockIdx.x * GBN;
    const int koff = blockIdx.z * (K / KSPLIT);
    const int lq   = lane >> 2;
    const int lr   = lane & 3;

    const int arow = t >> 1;
    const int ak8  = t & 1;
    const int brow = t >> 4;
    const int bcol = (t & 15) * 4;

    const float* Abase = A + (size_t)(m0 + arow) * K + koff + ak8 * 8;
    const float* Bbase = B + (size_t)(koff + brow) * N + n0 + bcol;

    uint32_t as_base = (uint32_t)__cvta_generic_to_shared(As) +
                       (arow * APITCH + ak8 * 8) * 4;
    uint32_t bs_base = (uint32_t)__cvta_generic_to_shared(Bs) +
                       (brow * 72 + bcol) * 4;

    float c[2][4][4];
#pragma unroll
    for (int mt = 0; mt < 2; mt++)
#pragma unroll
        for (int nt = 0; nt < 4; nt++)
#pragma unroll
            for (int i = 0; i < 4; i++) c[mt][nt][i] = 0.f;

    const int NSTEP = (K / KSPLIT) / GBK;

#pragma unroll
    for (int p = 0; p < NSTAGE - 1; p++) {
        if (p < NSTEP) {
            const float* asrc = Abase + p * GBK;
            uint32_t adst = as_base + p * A_STG * 4;
            CP_ASYNC16(adst, asrc);
            CP_ASYNC16(adst + 16, asrc + 4);
            const float* bsrc = Bbase + (size_t)p * GBK * N;
            CP_ASYNC16(bs_base + p * B_ST * 4, bsrc);
        }
        CP_COMMIT();
    }

    for (int s = 0; s < NSTEP; s++) {
        CP_WAIT2();
        __syncthreads();

        if (s + NSTAGE - 1 < NSTEP) {
            const int stg = (s + NSTAGE - 1) & (NSTAGE - 1);
            const float* asrc = Abase + (s + NSTAGE - 1) * GBK;
            uint32_t adst = as_base + stg * A_STG * 4;
            CP_ASYNC16(adst, asrc);
            CP_ASYNC16(adst + 16, asrc + 4);
            const float* bsrc = Bbase + (size_t)(s + NSTAGE - 1) * GBK * N;
            CP_ASYNC16(bs_base + stg * B_ST * 4, bsrc);
        }
        CP_COMMIT();

        const float* AsS = As + (s & (NSTAGE - 1)) * A_STG;
        const float* BsS = Bs + (s & (NSTAGE - 1)) * B_ST;

#pragma unroll
        for (int kk8 = 0; kk8 < 2; kk8++) {
            const int kb = kk8 * 8;
            uint32_t af[2][4];
#pragma unroll
            for (int mt = 0; mt < 2; mt++) {
                if (AINTER) {
                    const float2* AsS2 = (const float2*)AsS;
                    const int r0 = (wm + mt * 16 + lq) * (APITCH / 2) + kk8 * 4 + lr;
                    const float2 p0 = AsS2[r0];
                    const float2 p1 = AsS2[r0 + 8 * (APITCH / 2)];
                    af[mt][0] = __float_as_uint(p0.x);
                    af[mt][1] = __float_as_uint(p1.x);
                    af[mt][2] = __float_as_uint(p0.y);
                    af[mt][3] = __float_as_uint(p1.y);
                } else {
                    const int r0 = (wm + mt * 16 + lq) * APITCH;
                    af[mt][0] = __float_as_uint(AsS[r0 + kb + lr]);
                    af[mt][1] = __float_as_uint(AsS[r0 + 8 * APITCH + kb + lr]);
                    af[mt][2] = __float_as_uint(AsS[r0 + kb + lr + 4]);
                    af[mt][3] = __float_as_uint(AsS[r0 + 8 * APITCH + kb + lr + 4]);
                }
            }
            uint32_t bf[4][2];
#pragma unroll
            for (int nt = 0; nt < 4; nt++) {
                const int col = wn + nt * 8 + lq;
                bf[nt][0] = __float_as_uint(BsS[(kb + lr) * 72 + col]);
                bf[nt][1] = __float_as_uint(BsS[(kb + lr + 4) * 72 + col]);
            }
#pragma unroll
            for (int mt = 0; mt < 2; mt++)
#pragma unroll
                for (int nt = 0; nt < 4; nt++)
                    mma_tf32(c[mt][nt][0], c[mt][nt][1], c[mt][nt][2], c[mt][nt][3],
                             af[mt][0], af[mt][1], af[mt][2], af[mt][3],
                             bf[nt][0], bf[nt][1]);
        }
    }

#pragma unroll
    for (int mt = 0; mt < 2; mt++) {
#pragma unroll
        for (int nt = 0; nt < 4; nt++) {
            const int row0 = m0 + wm + mt * 16 + lq;
            const int col  = n0 + wn + nt * 8 + 2 * lr;
            if (ATOMIC) {
                atomicAdd(&Cout[(size_t)row0 * N + col],       c[mt][nt][0]);
                atomicAdd(&Cout[(size_t)row0 * N + col + 1],   c[mt][nt][1]);
                atomicAdd(&Cout[(size_t)(row0 + 8) * N + col],     c[mt][nt][2]);
                atomicAdd(&Cout[(size_t)(row0 + 8) * N + col + 1], c[mt][nt][3]);
            } else {
                *(float2*)&Cout[(size_t)row0 * N + col] =
                    make_float2(c[mt][nt][0], c[mt][nt][1]);
                *(float2*)&Cout[(size_t)(row0 + 8) * N + col] =
                    make_float2(c[mt][nt][2], c[mt][nt][3]);
            }
        }
    }
}

#define G1_SMEM_BYTES ((NSTAGE * (128 * 24) + NSTAGE * B_ST) * 4)
#define G2_SMEM_BYTES ((NSTAGE * (128 * 20) + NSTAGE * B_ST) * 4)

// ---------------------------------------------------------------------------
// Attention v7: attn5 structure (same phases, same syncs, V reg-prefetch)
// but K and V stored UNSPLIT fp32 in smem; hi/lo computed in-register at
// B-fragment load time. smem 69.8 KB -> 3 CTAs/SM.
//
// smem float layout (17440 floats = 69760 B):
//  [0,2176)       QH [32][68]     -> after A: WH [32][132] (4224 <= 4352)
//  [2176,4352)    QL [32][68]
//  [4352,13056)   KF [128][68]    -> VF [128][68] (plain fp32)
//  [13056,17280)  S  [32][132]    -> WL in place
//  [17280,17440)  nb[128], pts[32]
// ---------------------------------------------------------------------------
#define AST 68
#define BST 132
#define OFF_QH 0
#define OFF_QL 2176
#define OFF_KF 4352
#define OFF_S  13056
#define OFF_WH OFF_QH
#define OFF_WL OFF_S
#define OFF_VF OFF_KF
#define OFF_IDX 17280
#define ATTN_SMEM_FLOATS (OFF_IDX + BAND + QB)
#define ATTN_SMEM_BYTES  (ATTN_SMEM_FLOATS * 4)

__global__ void __launch_bounds__(256, 3) attn7_kernel(
    const float* __restrict__ qkv,
    const int* __restrict__ perms,
    float* __restrict__ y)
{
    extern __shared__ float sm[];
    int* nb  = (int*)(sm + OFF_IDX);
    int* pts = nb + BAND;

    const int h    = blockIdx.y;
    const int t0   = blockIdx.x * QB;
    const int t    = threadIdx.x;
    const int lane = t & 31;
    const int w    = t >> 5;
    const int lq   = lane >> 2;
    const int lr   = lane & 3;

    const int* __restrict__ perm = perms + h * TT;

    // ---- index staging ----
    for (int i = t; i < BAND + QB; i += 256) {
        if (i < BAND) {
            int j  = t0 - WINW + i;
            int jc = min(max(j, 0), TT - 1);
            nb[i] = perm[jc];
        } else {
            pts[i - BAND] = perm[t0 + (i - BAND)];
        }
    }
    __syncthreads();

    // ---- stage Q (scaled) split hi/lo (A-operand stays pre-split) ----
    {
        const int row = t >> 3;
        const int d0  = (t & 7) * 8;
        const float* src = qkv + (size_t)pts[row] * C3 + h * DHD + d0;
        float4 v0 = *(const float4*)src;
        float4 v1 = *(const float4*)(src + 4);
        float vv[8] = {v0.x, v0.y, v0.z, v0.w, v1.x, v1.y, v1.z, v1.w};
        float hi[8], lo[8];
#pragma unroll
        for (int i = 0; i < 8; i++) {
            float s = vv[i] * 0.125f;
            hi[i] = to_tf32(s);
            lo[i] = to_tf32(s - hi[i]);
        }
        const int o = row * AST + d0;
        *(float4*)&sm[OFF_QH + o]     = make_float4(hi[0], hi[1], hi[2], hi[3]);
        *(float4*)&sm[OFF_QH + o + 4] = make_float4(hi[4], hi[5], hi[6], hi[7]);
        *(float4*)&sm[OFF_QL + o]     = make_float4(lo[0], lo[1], lo[2], lo[3]);
        *(float4*)&sm[OFF_QL + o + 4] = make_float4(lo[4], lo[5], lo[6], lo[7]);
    }
    // ---- stage K plain fp32 ----
#pragma unroll
    for (int it = 0; it < 4; it++) {
        const int r  = it * 32 + (t >> 3);
        const int d0 = (t & 7) * 8;
        const float* src = qkv + (size_t)nb[r] * C3 + CC + h * DHD + d0;
        float4 v0 = *(const float4*)src;
        float4 v1 = *(const float4*)(src + 4);
        *(float4*)&sm[OFF_KF + r * AST + d0]     = v0;
        *(float4*)&sm[OFF_KF + r * AST + d0 + 4] = v1;
    }

    // ---- prefetch V into registers (LDGs overlap Phase A) ----
    float2 vr[16];
#pragma unroll
    for (int it = 0; it < 16; it++) {
        const int r = it * 8 + w;
        vr[it] = *(const float2*)&qkv[(size_t)nb[r] * C3 + 2 * CC + h * DHD + 2 * lane];
    }
    __syncthreads();

    // ---- Phase A: S = Q K^T, 3xTF32 (K split in-register) ----
    {
        float c[2][2][4];
#pragma unroll
        for (int mt = 0; mt < 2; mt++)
#pragma unroll
            for (int nt = 0; nt < 2; nt++)
#pragma unroll
                for (int i = 0; i < 4; i++) c[mt][nt][i] = 0.f;

#pragma unroll
        for (int kb = 0; kb < DHD; kb += 8) {
            uint32_t ah[2][4], al[2][4];
#pragma unroll
            for (int mt = 0; mt < 2; mt++) {
                const int r0 = (mt * 16 + lq) * AST + kb;
                ah[mt][0] = __float_as_uint(sm[OFF_QH + r0 + lr]);
                ah[mt][1] = __float_as_uint(sm[OFF_QH + r0 + 8 * AST + lr]);
                ah[mt][2] = __float_as_uint(sm[OFF_QH + r0 + lr + 4]);
                ah[mt][3] = __float_as_uint(sm[OFF_QH + r0 + 8 * AST + lr + 4]);
                al[mt][0] = __float_as_uint(sm[OFF_QL + r0 + lr]);
                al[mt][1] = __float_as_uint(sm[OFF_QL + r0 + 8 * AST + lr]);
                al[mt][2] = __float_as_uint(sm[OFF_QL + r0 + lr + 4]);
                al[mt][3] = __float_as_uint(sm[OFF_QL + r0 + 8 * AST + lr + 4]);
            }
            uint32_t bh[2][2], bl[2][2];
#pragma unroll
            for (int nt = 0; nt < 2; nt++) {
                const int co = (w * 16 + nt * 8 + lq) * AST + kb;
                split_tf32(sm[OFF_KF + co + lr],     bh[nt][0], bl[nt][0]);
                split_tf32(sm[OFF_KF + co + lr + 4], bh[nt][1], bl[nt][1]);
            }
#pragma unroll
            for (int mt = 0; mt < 2; mt++)
#pragma unroll
                for (int nt = 0; nt < 2; nt++) {
                    mma_tf32(c[mt][nt][0], c[mt][nt][1], c[mt][nt][2], c[mt][nt][3],
                             ah[mt][0], ah[mt][1], ah[mt][2], ah[mt][3],
                             bh[nt][0], bh[nt][1]);
                    mma_tf32(c[mt][nt][0], c[mt][nt][1], c[mt][nt][2], c[mt][nt][3],
                             ah[mt][0], ah[mt][1], ah[mt][2], ah[mt][3],
                             bl[nt][0], bl[nt][1]);
                    mma_tf32(c[mt][nt][0], c[mt][nt][1], c[mt][nt][2], c[mt][nt][3],
                             al[mt][0], al[mt][1], al[mt][2], al[mt][3],
                             bh[nt][0], bh[nt][1]);
                }
        }
#pragma unroll
        for (int mt = 0; mt < 2; mt++)
#pragma unroll
            for (int nt = 0; nt < 2; nt++) {
                const int q0  = mt * 16 + lq;
                const int col = w * 16 + nt * 8 + 2 * lr;
                *(float2*)&sm[OFF_S + q0 * BST + col] =
                    make_float2(c[mt][nt][0], c[mt][nt][1]);
                *(float2*)&sm[OFF_S + (q0 + 8) * BST + col] =
                    make_float2(c[mt][nt][2], c[mt][nt][3]);
            }
    }
    __syncthreads();

    // ---- store V from registers, plain fp32, natural [r][68] layout ----
#pragma unroll
    for (int it = 0; it < 16; it++) {
        const int r = it * 8 + w;
        *(float2*)&sm[OFF_VF + r * AST + 2 * lane] = vr[it];
    }

    // ---- masked softmax; W split (WH over Q region, WL in-place over S) ----
    for (int qq = w; qq < QB; qq += 8) {
        const int pt = pts[qq];
        float v[4];
#pragma unroll
        for (int cc = 0; cc < 4; cc++) {
            const int r = lane + 32 * cc;
            const bool m = (r >= qq) && (r <= qq + 96) &&
                           ((unsigned)(t0 - WINW + r) < (unsigned)TT) &&
                           (nb[r] <= pt);
            v[cc] = m ? sm[OFF_S + qq * BST + r] : -INFINITY;
        }
        float mx = fmaxf(fmaxf(v[0], v[1]), fmaxf(v[2], v[3]));
#pragma unroll
        for (int off = 16; off; off >>= 1)
            mx = fmaxf(mx, __shfl_xor_sync(0xffffffffu, mx, off));
        float e[4], s = 0.f;
#pragma unroll
        for (int cc = 0; cc < 4; cc++) { e[cc] = __expf(v[cc] - mx); s += e[cc]; }
#pragma unroll
        for (int off = 16; off; off >>= 1)
            s += __shfl_xor_sync(0xffffffffu, s, off);
        const float inv = 1.f / s;
#pragma unroll
        for (int cc = 0; cc < 4; cc++) {
            const int r = lane + 32 * cc;
            const float wv = e[cc] * inv;
            const float hi = to_tf32(wv);
            sm[OFF_WH + qq * BST + r] = hi;
            sm[OFF_WL + qq * BST + r] = to_tf32(wv - hi);
        }
    }
    __syncthreads();

    // ---- Phase B: Y = W V, 3xTF32 (V split in-register) ----
    {
        const int wm = (w & 1) * 16;
        const int ng = (w >> 1) * 16;
        float c[2][4];
#pragma unroll
        for (int nt = 0; nt < 2; nt++)
#pragma unroll
            for (int i = 0; i < 4; i++) c[nt][i] = 0.f;

#pragma unroll
        for (int kb = 0; kb < BAND; kb += 8) {
            uint32_t ah[4], al[4];
            const int r0 = (wm + lq) * BST + kb;
            ah[0] = __float_as_uint(sm[OFF_WH + r0 + lr]);
            ah[1] = __float_as_uint(sm[OFF_WH + r0 + 8 * BST + lr]);
            ah[2] = __float_as_uint(sm[OFF_WH + r0 + lr + 4]);
            ah[3] = __float_as_uint(sm[OFF_WH + r0 + 8 * BST + lr + 4]);
            al[0] = __float_as_uint(sm[OFF_WL + r0 + lr]);
            al[1] = __float_as_uint(sm[OFF_WL + r0 + 8 * BST + lr]);
            al[2] = __float_as_uint(sm[OFF_WL + r0 + lr + 4]);
            al[3] = __float_as_uint(sm[OFF_WL + r0 + 8 * BST + lr + 4]);
            uint32_t bh[2][2], bl[2][2];
#pragma unroll
            for (int nt = 0; nt < 2; nt++) {
                const int col = ng + nt * 8 + lq;
                split_tf32(sm[OFF_VF + (kb + lr) * AST + col],     bh[nt][0], bl[nt][0]);
                split_tf32(sm[OFF_VF + (kb + lr + 4) * AST + col], bh[nt][1], bl[nt][1]);
            }
#pragma unroll
            for (int nt = 0; nt < 2; nt++) {
                mma_tf32(c[nt][0], c[nt][1], c[nt][2], c[nt][3],
                         ah[0], ah[1], ah[2], ah[3], bh[nt][0], bh[nt][1]);
                mma_tf32(c[nt][0], c[nt][1], c[nt][2], c[nt][3],
                         ah[0], ah[1], ah[2], ah[3], bl[nt][0], bl[nt][1]);
                mma_tf32(c[nt][0], c[nt][1], c[nt][2], c[nt][3],
                         al[0], al[1], al[2], al[3], bh[nt][0], bh[nt][1]);
            }
        }

#pragma unroll
        for (int nt = 0; nt < 2; nt++) {
            const int d  = ng + nt * 8 + 2 * lr;
            const int q0 = wm + lq;
            *(float2*)&y[(size_t)pts[q0] * CC + h * DHD + d] =
                make_float2(to_tf32(c[nt][0]), to_tf32(c[nt][1]));
            *(float2*)&y[(size_t)pts[q0 + 8] * CC + h * DHD + d] =
                make_float2(to_tf32(c[nt][2]), to_tf32(c[nt][3]));
        }
    }
}

// ---------------------------------------------------------------------------
extern "C" void kernel_launch(void* const* d_in, const int* in_sizes, int n_in,
                              void* d_out, int out_size) {
    (void)in_sizes; (void)n_in; (void)out_size;
    const float* x     = (const float*)d_in[0];
    const float* Wqkv  = (const float*)d_in[1];
    const float* Wout  = (const float*)d_in[2];
    const int*   perms = (const int*)d_in[3];
    float*       out   = (float*)d_out;

    float *qkv, *y, *x32, *wq32, *wo32;
    cudaGetSymbolAddress((void**)&qkv,  g_qkv);
    cudaGetSymbolAddress((void**)&y,    g_y);
    cudaGetSymbolAddress((void**)&x32,  g_x32);
    cudaGetSymbolAddress((void**)&wq32, g_wqkv32);
    cudaGetSymbolAddress((void**)&wo32, g_wout32);

    cudaFuncSetAttribute((const void*)gemm_tf32_kernel<TT, C3, CC, 1, false, true>,
                         cudaFuncAttributeMaxDynamicSharedMemorySize, G1_SMEM_BYTES);
    cudaFuncSetAttribute((const void*)gemm_tf32_kernel<TT, CC, CC, 4, true, false>,
                         cudaFuncAttributeMaxDynamicSharedMemorySize, G2_SMEM_BYTES);
    cudaFuncSetAttribute(attn7_kernel,
                         cudaFuncAttributeMaxDynamicSharedMemorySize, ATTN_SMEM_BYTES);

    // 0) tf32-round + interleave x, round weights, zero split-K target
    prep_tf32_kernel<<<(PREPTH + 255) / 256, 256>>>(
        (const float4*)x, (const float4*)Wqkv, (const float4*)Wout,
        (float4*)x32, (float4*)wq32, (float4*)wo32, (float4*)out);
    // 1) qkv = x @ W_qkv  (interleaved-A fragment path)
    gemm_tf32_kernel<TT, C3, CC, 1, false, true>
        <<<dim3(C3 / GBN, TT / GBM, 1), 256, G1_SMEM_BYTES>>>(x32, wq32, qkv);
    // 2) attention (3 CTAs/SM, attn5 structure, in-register B-splits)
    attn7_kernel<<<dim3(TT / QB, HH), 256, ATTN_SMEM_BYTES>>>(qkv, perms, y);
    // 3) out += y @ W_out (split-K=4, atomic accumulate)
    gemm_tf32_kernel<TT, CC, CC, 4, true, false>
        <<<dim3(CC / GBN, TT / GBM, 4), 256, G2_SMEM_BYTES>>>(y, wo32, out);
}

// round 14
// speedup vs baseline: 1.1859x; 1.0478x over previous
#include <cuda_runtime.h>
#include <math.h>
#include <stdint.h>

#define TT   2048
#define CC   512
#define HH   8
#define DHD  64
#define WINW 48
#define C3   1536
#define QB   32
#define BAND 128

// Scratch (device globals — no allocation allowed)
__device__ float g_qkv[TT * C3];
__device__ float g_y[TT * CC];
__device__ float g_x32[TT * CC];      // tf32-rounded x, 8-chunk pair-interleaved
__device__ float g_wqkv32[CC * C3];   // tf32-rounded W_qkv (plain)
__device__ float g_wout32[CC * CC];   // tf32-rounded W_out (plain)

// ---------------------------------------------------------------------------
__device__ __forceinline__ float to_tf32(float x) {
    float y;
    asm("cvt.rna.tf32.f32 %0, %1;" : "=f"(y) : "f"(x));
    return y;
}

__device__ __forceinline__ void split_tf32(float v, uint32_t& hi, uint32_t& lo) {
    float h = to_tf32(v);
    float l = to_tf32(v - h);
    hi = __float_as_uint(h);
    lo = __float_as_uint(l);
}

__device__ __forceinline__ void mma_tf32(float& c0, float& c1, float& c2, float& c3,
                                         uint32_t a0, uint32_t a1, uint32_t a2, uint32_t a3,
                                         uint32_t b0, uint32_t b1) {
    asm volatile(
        "mma.sync.aligned.m16n8k8.row.col.f32.tf32.tf32.f32 "
        "{%0,%1,%2,%3}, {%4,%5,%6,%7}, {%8,%9}, {%0,%1,%2,%3};"
        : "+f"(c0), "+f"(c1), "+f"(c2), "+f"(c3)
        : "r"(a0), "r"(a1), "r"(a2), "r"(a3), "r"(b0), "r"(b1));
}

#define CP_ASYNC16(dst, src) \
    asm volatile("cp.async.cg.shared.global [%0], [%1], 16;\n" :: "r"(dst), "l"(src))
#define CP_COMMIT() asm volatile("cp.async.commit_group;\n" ::)
#define CP_WAIT2()  asm volatile("cp.async.wait_group 2;\n" ::)

// ---------------------------------------------------------------------------
// Prep: tf32-round x (pair-interleaved), W_qkv, W_out; zero `out`.
// ---------------------------------------------------------------------------
#define XCH   (TT * CC / 8)
#define WQF4  (CC * C3 / 4)
#define WOF4  (CC * CC / 4)
#define OUTF4 (TT * CC / 4)
#define PREPTH (XCH + WQF4 + WOF4 + OUTF4)

__global__ void prep_tf32_kernel(const float4* __restrict__ x,
                                 const float4* __restrict__ wq,
                                 const float4* __restrict__ wo,
                                 float4* __restrict__ xo,
                                 float4* __restrict__ wqo,
                                 float4* __restrict__ woo,
                                 float4* __restrict__ outz) {
    int i = blockIdx.x * blockDim.x + threadIdx.x;
    if (i >= PREPTH) return;
    if (i < XCH) {
        const float4 a = x[2 * i];
        const float4 b = x[2 * i + 1];
        float4 o0, o1;
        o0.x = to_tf32(a.x); o0.y = to_tf32(b.x);
        o0.z = to_tf32(a.y); o0.w = to_tf32(b.y);
        o1.x = to_tf32(a.z); o1.y = to_tf32(b.z);
        o1.z = to_tf32(a.w); o1.w = to_tf32(b.w);
        xo[2 * i]     = o0;
        xo[2 * i + 1] = o1;
        return;
    }
    i -= XCH;
    if (i < WQF4) {
        float4 v = wq[i];
        v.x = to_tf32(v.x); v.y = to_tf32(v.y);
        v.z = to_tf32(v.z); v.w = to_tf32(v.w);
        wqo[i] = v;
        return;
    }
    i -= WQF4;
    if (i < WOF4) {
        float4 v = wo[i];
        v.x = to_tf32(v.x); v.y = to_tf32(v.y);
        v.z = to_tf32(v.z); v.w = to_tf32(v.w);
        woo[i] = v;
        return;
    }
    i -= WOF4;
    outz[i] = make_float4(0.f, 0.f, 0.f, 0.f);
}

// ---------------------------------------------------------------------------
// TF32 GEMM: cp.async 4-stage, block 128x64, 8 warps; split-K atomic option;
// AINTER = pair-interleaved A layout (LDS.64 fragments). PDL-aware: waits on
// the producer grid before touching A/B.
// ---------------------------------------------------------------------------
#define GBM 128
#define GBN 64
#define GBK 16
#define NSTAGE 4
#define B_ST (16 * 72)

template<int M, int N, int K, int KSPLIT, bool ATOMIC, bool AINTER>
__global__ void __launch_bounds__(256, 3) gemm_tf32_kernel(
    const float* __restrict__ A,
    const float* __restrict__ B,
    float* __restrict__ Cout)
{
    constexpr int APITCH = AINTER ? 24 : 20;
    constexpr int A_STG  = 128 * APITCH;

    extern __shared__ float smemf[];
    float* As = smemf;
    float* Bs = smemf + NSTAGE * A_STG;

    const int t    = threadIdx.x;
    const int lane = t & 31;
    const int w    = t >> 5;
    const int wm   = (w >> 1) * 32;
    const int wn   = (w & 1) * 32;
    const int m0   = blockIdx.y * GBM;
    const int n0   = blockIdx.x * GBN;
    const int koff = blockIdx.z * (K / KSPLIT);
    const int lq   = lane >> 2;
    const int lr   = lane & 3;

    const int arow = t >> 1;
    const int ak8  = t & 1;
    const int brow = t >> 4;
    const int bcol = (t & 15) * 4;

    const float* Abase = A + (size_t)(m0 + arow) * K + koff + ak8 * 8;
    const float* Bbase = B + (size_t)(koff + brow) * N + n0 + bcol;

    uint32_t as_base = (uint32_t)__cvta_generic_to_shared(As) +
                       (arow * APITCH + ak8 * 8) * 4;
    uint32_t bs_base = (uint32_t)__cvta_generic_to_shared(Bs) +
                       (brow * 72 + bcol) * 4;

    float c[2][4][4];
#pragma unroll
    for (int mt = 0; mt < 2; mt++)
#pragma unroll
        for (int nt = 0; nt < 4; nt++)
#pragma unroll
            for (int i = 0; i < 4; i++) c[mt][nt][i] = 0.f;

    const int NSTEP = (K / KSPLIT) / GBK;

    // PDL: wait for producer grid before reading its output
    cudaGridDependencySynchronize();

#pragma unroll
    for (int p = 0; p < NSTAGE - 1; p++) {
        if (p < NSTEP) {
            const float* asrc = Abase + p * GBK;
            uint32_t adst = as_base + p * A_STG * 4;
            CP_ASYNC16(adst, asrc);
            CP_ASYNC16(adst + 16, asrc + 4);
            const float* bsrc = Bbase + (size_t)p * GBK * N;
            CP_ASYNC16(bs_base + p * B_ST * 4, bsrc);
        }
        CP_COMMIT();
    }

    for (int s = 0; s < NSTEP; s++) {
        CP_WAIT2();
        __syncthreads();

        if (s + NSTAGE - 1 < NSTEP) {
            const int stg = (s + NSTAGE - 1) & (NSTAGE - 1);
            const float* asrc = Abase + (s + NSTAGE - 1) * GBK;
            uint32_t adst = as_base + stg * A_STG * 4;
            CP_ASYNC16(adst, asrc);
            CP_ASYNC16(adst + 16, asrc + 4);
            const float* bsrc = Bbase + (size_t)(s + NSTAGE - 1) * GBK * N;
            CP_ASYNC16(bs_base + stg * B_ST * 4, bsrc);
        }
        CP_COMMIT();

        const float* AsS = As + (s & (NSTAGE - 1)) * A_STG;
        const float* BsS = Bs + (s & (NSTAGE - 1)) * B_ST;

#pragma unroll
        for (int kk8 = 0; kk8 < 2; kk8++) {
            const int kb = kk8 * 8;
            uint32_t af[2][4];
#pragma unroll
            for (int mt = 0; mt < 2; mt++) {
                if (AINTER) {
                    const float2* AsS2 = (const float2*)AsS;
                    const int r0 = (wm + mt * 16 + lq) * (APITCH / 2) + kk8 * 4 + lr;
                    const float2 p0 = AsS2[r0];
                    const float2 p1 = AsS2[r0 + 8 * (APITCH / 2)];
                    af[mt][0] = __float_as_uint(p0.x);
                    af[mt][1] = __float_as_uint(p1.x);
                    af[mt][2] = __float_as_uint(p0.y);
                    af[mt][3] = __float_as_uint(p1.y);
                } else {
                    const int r0 = (wm + mt * 16 + lq) * APITCH;
                    af[mt][0] = __float_as_uint(AsS[r0 + kb + lr]);
                    af[mt][1] = __float_as_uint(AsS[r0 + 8 * APITCH + kb + lr]);
                    af[mt][2] = __float_as_uint(AsS[r0 + kb + lr + 4]);
                    af[mt][3] = __float_as_uint(AsS[r0 + 8 * APITCH + kb + lr + 4]);
                }
            }
            uint32_t bf[4][2];
#pragma unroll
            for (int nt = 0; nt < 4; nt++) {
                const int col = wn + nt * 8 + lq;
                bf[nt][0] = __float_as_uint(BsS[(kb + lr) * 72 + col]);
                bf[nt][1] = __float_as_uint(BsS[(kb + lr + 4) * 72 + col]);
            }
#pragma unroll
            for (int mt = 0; mt < 2; mt++)
#pragma unroll
                for (int nt = 0; nt < 4; nt++)
                    mma_tf32(c[mt][nt][0], c[mt][nt][1], c[mt][nt][2], c[mt][nt][3],
                             af[mt][0], af[mt][1], af[mt][2], af[mt][3],
                             bf[nt][0], bf[nt][1]);
        }
    }

#pragma unroll
    for (int mt = 0; mt < 2; mt++) {
#pragma unroll
        for (int nt = 0; nt < 4; nt++) {
            const int row0 = m0 + wm + mt * 16 + lq;
            const int col  = n0 + wn + nt * 8 + 2 * lr;
            if (ATOMIC) {
                atomicAdd(&Cout[(size_t)row0 * N + col],       c[mt][nt][0]);
                atomicAdd(&Cout[(size_t)row0 * N + col + 1],   c[mt][nt][1]);
                atomicAdd(&Cout[(size_t)(row0 + 8) * N + col],     c[mt][nt][2]);
                atomicAdd(&Cout[(size_t)(row0 + 8) * N + col + 1], c[mt][nt][3]);
            } else {
                *(float2*)&Cout[(size_t)row0 * N + col] =
                    make_float2(c[mt][nt][0], c[mt][nt][1]);
                *(float2*)&Cout[(size_t)(row0 + 8) * N + col] =
                    make_float2(c[mt][nt][2], c[mt][nt][3]);
            }
        }
    }
}

#define G1_SMEM_BYTES ((NSTAGE * (128 * 24) + NSTAGE * B_ST) * 4)
#define G2_SMEM_BYTES ((NSTAGE * (128 * 20) + NSTAGE * B_ST) * 4)

// ---------------------------------------------------------------------------
// Attention v7 (R13, best): attn5 phases, K/V unsplit fp32 in smem, hi/lo
// B-splits in-register, 3 CTAs/SM. PDL-aware: perm-index staging happens
// BEFORE the grid-dependency sync (it reads only kernel inputs).
// ---------------------------------------------------------------------------
#define AST 68
#define BST 132
#define OFF_QH 0
#define OFF_QL 2176
#define OFF_KF 4352
#define OFF_S  13056
#define OFF_WH OFF_QH
#define OFF_WL OFF_S
#define OFF_VF OFF_KF
#define OFF_IDX 17280
#define ATTN_SMEM_FLOATS (OFF_IDX + BAND + QB)
#define ATTN_SMEM_BYTES  (ATTN_SMEM_FLOATS * 4)

__global__ void __launch_bounds__(256, 3) attn7_kernel(
    const float* __restrict__ qkv,
    const int* __restrict__ perms,
    float* __restrict__ y)
{
    extern __shared__ float sm[];
    int* nb  = (int*)(sm + OFF_IDX);
    int* pts = nb + BAND;

    const int h    = blockIdx.y;
    const int t0   = blockIdx.x * QB;
    const int t    = threadIdx.x;
    const int lane = t & 31;
    const int w    = t >> 5;
    const int lq   = lane >> 2;
    const int lr   = lane & 3;

    const int* __restrict__ perm = perms + h * TT;

    // ---- index staging (reads kernel inputs only -> overlaps producer) ----
    for (int i = t; i < BAND + QB; i += 256) {
        if (i < BAND) {
            int j  = t0 - WINW + i;
            int jc = min(max(j, 0), TT - 1);
            nb[i] = perm[jc];
        } else {
            pts[i - BAND] = perm[t0 + (i - BAND)];
        }
    }
    __syncthreads();

    // PDL: qkv (gemm1 output) must be complete beyond this point
    cudaGridDependencySynchronize();

    // ---- stage Q (scaled) split hi/lo ----
    {
        const int row = t >> 3;
        const int d0  = (t & 7) * 8;
        const float* src = qkv + (size_t)pts[row] * C3 + h * DHD + d0;
        float4 v0 = *(const float4*)src;
        float4 v1 = *(const float4*)(src + 4);
        float vv[8] = {v0.x, v0.y, v0.z, v0.w, v1.x, v1.y, v1.z, v1.w};
        float hi[8], lo[8];
#pragma unroll
        for (int i = 0; i < 8; i++) {
            float s = vv[i] * 0.125f;
            hi[i] = to_tf32(s);
            lo[i] = to_tf32(s - hi[i]);
        }
        const int o = row * AST + d0;
        *(float4*)&sm[OFF_QH + o]     = make_float4(hi[0], hi[1], hi[2], hi[3]);
        *(float4*)&sm[OFF_QH + o + 4] = make_float4(hi[4], hi[5], hi[6], hi[7]);
        *(float4*)&sm[OFF_QL + o]     = make_float4(lo[0], lo[1], lo[2], lo[3]);
        *(float4*)&sm[OFF_QL + o + 4] = make_float4(lo[4], lo[5], lo[6], lo[7]);
    }
    // ---- stage K plain fp32 ----
#pragma unroll
    for (int it = 0; it < 4; it++) {
        const int r  = it * 32 + (t >> 3);
        const int d0 = (t & 7) * 8;
        const float* src = qkv + (size_t)nb[r] * C3 + CC + h * DHD + d0;
        float4 v0 = *(const float4*)src;
        float4 v1 = *(const float4*)(src + 4);
        *(float4*)&sm[OFF_KF + r * AST + d0]     = v0;
        *(float4*)&sm[OFF_KF + r * AST + d0 + 4] = v1;
    }

    // ---- prefetch V into registers (LDGs overlap Phase A) ----
    float2 vr[16];
#pragma unroll
    for (int it = 0; it < 16; it++) {
        const int r = it * 8 + w;
        vr[it] = *(const float2*)&qkv[(size_t)nb[r] * C3 + 2 * CC + h * DHD + 2 * lane];
    }
    __syncthreads();

    // ---- Phase A: S = Q K^T, 3xTF32 (K split in-register) ----
    {
        float c[2][2][4];
#pragma unroll
        for (int mt = 0; mt < 2; mt++)
#pragma unroll
            for (int nt = 0; nt < 2; nt++)
#pragma unroll
                for (int i = 0; i < 4; i++) c[mt][nt][i] = 0.f;

#pragma unroll
        for (int kb = 0; kb < DHD; kb += 8) {
            uint32_t ah[2][4], al[2][4];
#pragma unroll
            for (int mt = 0; mt < 2; mt++) {
                const int r0 = (mt * 16 + lq) * AST + kb;
                ah[mt][0] = __float_as_uint(sm[OFF_QH + r0 + lr]);
                ah[mt][1] = __float_as_uint(sm[OFF_QH + r0 + 8 * AST + lr]);
                ah[mt][2] = __float_as_uint(sm[OFF_QH + r0 + lr + 4]);
                ah[mt][3] = __float_as_uint(sm[OFF_QH + r0 + 8 * AST + lr + 4]);
                al[mt][0] = __float_as_uint(sm[OFF_QL + r0 + lr]);
                al[mt][1] = __float_as_uint(sm[OFF_QL + r0 + 8 * AST + lr]);
                al[mt][2] = __float_as_uint(sm[OFF_QL + r0 + lr + 4]);
                al[mt][3] = __float_as_uint(sm[OFF_QL + r0 + 8 * AST + lr + 4]);
            }
            uint32_t bh[2][2], bl[2][2];
#pragma unroll
            for (int nt = 0; nt < 2; nt++) {
                const int co = (w * 16 + nt * 8 + lq) * AST + kb;
                split_tf32(sm[OFF_KF + co + lr],     bh[nt][0], bl[nt][0]);
                split_tf32(sm[OFF_KF + co + lr + 4], bh[nt][1], bl[nt][1]);
            }
#pragma unroll
            for (int mt = 0; mt < 2; mt++)
#pragma unroll
                for (int nt = 0; nt < 2; nt++) {
                    mma_tf32(c[mt][nt][0], c[mt][nt][1], c[mt][nt][2], c[mt][nt][3],
                             ah[mt][0], ah[mt][1], ah[mt][2], ah[mt][3],
                             bh[nt][0], bh[nt][1]);
                    mma_tf32(c[mt][nt][0], c[mt][nt][1], c[mt][nt][2], c[mt][nt][3],
                             ah[mt][0], ah[mt][1], ah[mt][2], ah[mt][3],
                             bl[nt][0], bl[nt][1]);
                    mma_tf32(c[mt][nt][0], c[mt][nt][1], c[mt][nt][2], c[mt][nt][3],
                             al[mt][0], al[mt][1], al[mt][2], al[mt][3],
                             bh[nt][0], bh[nt][1]);
                }
        }
#pragma unroll
        for (int mt = 0; mt < 2; mt++)
#pragma unroll
            for (int nt = 0; nt < 2; nt++) {
                const int q0  = mt * 16 + lq;
                const int col = w * 16 + nt * 8 + 2 * lr;
                *(float2*)&sm[OFF_S + q0 * BST + col] =
                    make_float2(c[mt][nt][0], c[mt][nt][1]);
                *(float2*)&sm[OFF_S + (q0 + 8) * BST + col] =
                    make_float2(c[mt][nt][2], c[mt][nt][3]);
            }
    }
    __syncthreads();

    // ---- store V from registers, plain fp32, natural [r][68] layout ----
#pragma unroll
    for (int it = 0; it < 16; it++) {
        const int r = it * 8 + w;
        *(float2*)&sm[OFF_VF + r * AST + 2 * lane] = vr[it];
    }

    // ---- masked softmax; W split (WH over Q region, WL in-place over S) ----
    for (int qq = w; qq < QB; qq += 8) {
        const int pt = pts[qq];
        float v[4];
#pragma unroll
        for (int cc = 0; cc < 4; cc++) {
            const int r = lane + 32 * cc;
            const bool m = (r >= qq) && (r <= qq + 96) &&
                           ((unsigned)(t0 - WINW + r) < (unsigned)TT) &&
                           (nb[r] <= pt);
            v[cc] = m ? sm[OFF_S + qq * BST + r] : -INFINITY;
        }
        float mx = fmaxf(fmaxf(v[0], v[1]), fmaxf(v[2], v[3]));
#pragma unroll
        for (int off = 16; off; off >>= 1)
            mx = fmaxf(mx, __shfl_xor_sync(0xffffffffu, mx, off));
        float e[4], s = 0.f;
#pragma unroll
        for (int cc = 0; cc < 4; cc++) { e[cc] = __expf(v[cc] - mx); s += e[cc]; }
#pragma unroll
        for (int off = 16; off; off >>= 1)
            s += __shfl_xor_sync(0xffffffffu, s, off);
        const float inv = 1.f / s;
#pragma unroll
        for (int cc = 0; cc < 4; cc++) {
            const int r = lane + 32 * cc;
            const float wv = e[cc] * inv;
            const float hi = to_tf32(wv);
            sm[OFF_WH + qq * BST + r] = hi;
            sm[OFF_WL + qq * BST + r] = to_tf32(wv - hi);
        }
    }
    __syncthreads();

    // ---- Phase B: Y = W V, 3xTF32 (V split in-register) ----
    {
        const int wm = (w & 1) * 16;
        const int ng = (w >> 1) * 16;
        float c[2][4];
#pragma unroll
        for (int nt = 0; nt < 2; nt++)
#pragma unroll
            for (int i = 0; i < 4; i++) c[nt][i] = 0.f;

#pragma unroll
        for (int kb = 0; kb < BAND; kb += 8) {
            uint32_t ah[4], al[4];
            const int r0 = (wm + lq) * BST + kb;
            ah[0] = __float_as_uint(sm[OFF_WH + r0 + lr]);
            ah[1] = __float_as_uint(sm[OFF_WH + r0 + 8 * BST + lr]);
            ah[2] = __float_as_uint(sm[OFF_WH + r0 + lr + 4]);
            ah[3] = __float_as_uint(sm[OFF_WH + r0 + 8 * BST + lr + 4]);
            al[0] = __float_as_uint(sm[OFF_WL + r0 + lr]);
            al[1] = __float_as_uint(sm[OFF_WL + r0 + 8 * BST + lr]);
            al[2] = __float_as_uint(sm[OFF_WL + r0 + lr + 4]);
            al[3] = __float_as_uint(sm[OFF_WL + r0 + 8 * BST + lr + 4]);
            uint32_t bh[2][2], bl[2][2];
#pragma unroll
            for (int nt = 0; nt < 2; nt++) {
                const int col = ng + nt * 8 + lq;
                split_tf32(sm[OFF_VF + (kb + lr) * AST + col],     bh[nt][0], bl[nt][0]);
                split_tf32(sm[OFF_VF + (kb + lr + 4) * AST + col], bh[nt][1], bl[nt][1]);
            }
#pragma unroll
            for (int nt = 0; nt < 2; nt++) {
                mma_tf32(c[nt][0], c[nt][1], c[nt][2], c[nt][3],
                         ah[0], ah[1], ah[2], ah[3], bh[nt][0], bh[nt][1]);
                mma_tf32(c[nt][0], c[nt][1], c[nt][2], c[nt][3],
                         ah[0], ah[1], ah[2], ah[3], bl[nt][0], bl[nt][1]);
                mma_tf32(c[nt][0], c[nt][1], c[nt][2], c[nt][3],
                         al[0], al[1], al[2], al[3], bh[nt][0], bh[nt][1]);
            }
        }

#pragma unroll
        for (int nt = 0; nt < 2; nt++) {
            const int d  = ng + nt * 8 + 2 * lr;
            const int q0 = wm + lq;
            *(float2*)&y[(size_t)pts[q0] * CC + h * DHD + d] =
                make_float2(to_tf32(c[nt][0]), to_tf32(c[nt][1]));
            *(float2*)&y[(size_t)pts[q0 + 8] * CC + h * DHD + d] =
                make_float2(to_tf32(c[nt][2]), to_tf32(c[nt][3]));
        }
    }
}

// ---------------------------------------------------------------------------
extern "C" void kernel_launch(void* const* d_in, const int* in_sizes, int n_in,
                              void* d_out, int out_size) {
    (void)in_sizes; (void)n_in; (void)out_size;
    const float* x     = (const float*)d_in[0];
    const float* Wqkv  = (const float*)d_in[1];
    const float* Wout  = (const float*)d_in[2];
    const int*   perms = (const int*)d_in[3];
    float*       out   = (float*)d_out;

    float *qkv, *y, *x32, *wq32, *wo32;
    cudaGetSymbolAddress((void**)&qkv,  g_qkv);
    cudaGetSymbolAddress((void**)&y,    g_y);
    cudaGetSymbolAddress((void**)&x32,  g_x32);
    cudaGetSymbolAddress((void**)&wq32, g_wqkv32);
    cudaGetSymbolAddress((void**)&wo32, g_wout32);

    cudaFuncSetAttribute((const void*)gemm_tf32_kernel<TT, C3, CC, 1, false, true>,
                         cudaFuncAttributeMaxDynamicSharedMemorySize, G1_SMEM_BYTES);
    cudaFuncSetAttribute((const void*)gemm_tf32_kernel<TT, CC, CC, 2, true, false>,
                         cudaFuncAttributeMaxDynamicSharedMemorySize, G2_SMEM_BYTES);
    cudaFuncSetAttribute(attn7_kernel,
                         cudaFuncAttributeMaxDynamicSharedMemorySize, ATTN_SMEM_BYTES);

    // PDL launch attribute (programmatic stream serialization)
    cudaLaunchAttribute pdl_attr;
    pdl_attr.id = cudaLaunchAttributeProgrammaticStreamSerialization;
    pdl_attr.val.programmaticStreamSerializationAllowed = 1;

    // 0) prep (plain launch; nothing upstream)
    prep_tf32_kernel<<<(PREPTH + 255) / 256, 256>>>(
        (const float4*)x, (const float4*)Wqkv, (const float4*)Wout,
        (float4*)x32, (float4*)wq32, (float4*)wo32, (float4*)out);

    // 1) qkv = x32 @ wq32  (PDL over prep)
    {
        cudaLaunchConfig_t cfg = {};
        cfg.gridDim = dim3(C3 / GBN, TT / GBM, 1);
        cfg.blockDim = dim3(256, 1, 1);
        cfg.dynamicSmemBytes = G1_SMEM_BYTES;
        cfg.stream = 0;
        cfg.attrs = &pdl_attr;
        cfg.numAttrs = 1;
        cudaLaunchKernelEx(&cfg, gemm_tf32_kernel<TT, C3, CC, 1, false, true>,
                           (const float*)x32, (const float*)wq32, qkv);
    }
    // 2) attention (PDL over gemm1; perm staging overlaps gemm1 tail)
    {
        cudaLaunchConfig_t cfg = {};
        cfg.gridDim = dim3(TT / QB, HH, 1);
        cfg.blockDim = dim3(256, 1, 1);
        cfg.dynamicSmemBytes = ATTN_SMEM_BYTES;
        cfg.stream = 0;
        cfg.attrs = &pdl_attr;
        cfg.numAttrs = 1;
        cudaLaunchKernelEx(&cfg, attn7_kernel,
                           (const float*)qkv, (const int*)perms, y);
    }
    // 3) out += y @ wo32 (split-K=2, PDL over attention)
    {
        cudaLaunchConfig_t cfg = {};
        cfg.gridDim = dim3(CC / GBN, TT / GBM, 2);
        cfg.blockDim = dim3(256, 1, 1);
        cfg.dynamicSmemBytes = G2_SMEM_BYTES;
        cfg.stream = 0;
        cfg.attrs = &pdl_attr;
        cfg.numAttrs = 1;
        cudaLaunchKernelEx(&cfg, gemm_tf32_kernel<TT, CC, CC, 2, true, false>,
                           (const float*)y, (const float*)wo32, out);
    }
}